// round 9
// baseline (speedup 1.0000x reference)
#include <cuda_runtime.h>
#include <math.h>

#define BB 2
#define TT 6
#define PP 20480
#define NTOK (BB*TT*PP)      /* 245760 */
#define DPROJ 266

// ---------------- scratch ----------------
__device__ float S_yf[(size_t)NTOK*128];
__device__ float S_yb[(size_t)NTOK*128];
__device__ int   Goff[NTOK];
// pre-permuted tf32 weights (B operands, n-major, kperm16'd)
__device__ unsigned Wp1[320*128];
__device__ unsigned WoP[96*128];
__device__ unsigned W1P[96*96];
__device__ unsigned W2P[96*96];

__device__ __forceinline__ float geluf(float v) {
    return 0.5f * v * (1.0f + erff(v * 0.70710678118654752f));
}
__device__ __forceinline__ unsigned f2tf32(float f) {
    unsigned r;
    asm("cvt.rna.tf32.f32 %0, %1;" : "=r"(r) : "f"(f));
    return r;
}
__device__ __forceinline__ int kperm16(int k) {
    int g = k & ~15, j = k & 15;
    return g + ((j & 3) << 2) + (j >> 2);
}
__device__ __forceinline__ void mma_tf32(float* c, const unsigned* a, const unsigned* b) {
    asm volatile(
        "mma.sync.aligned.m16n8k8.row.col.f32.tf32.tf32.f32 "
        "{%0,%1,%2,%3}, {%4,%5,%6,%7}, {%8,%9}, {%0,%1,%2,%3};"
        : "+f"(c[0]), "+f"(c[1]), "+f"(c[2]), "+f"(c[3])
        : "r"(a[0]), "r"(a[1]), "r"(a[2]), "r"(a[3]), "r"(b[0]), "r"(b[1]));
}
__device__ __forceinline__ void stage4(unsigned* row, int sw, int c, float x, float y, float z, float w) {
    int g = (c >> 2) << 4, r = c & 3;
    row[(g + r     ) ^ sw] = f2tf32(x);
    row[(g + r + 4 ) ^ sw] = f2tf32(y);
    row[(g + r + 8 ) ^ sw] = f2tf32(z);
    row[(g + r + 12) ^ sw] = f2tf32(w);
}

// ================= prep: weights + gather offsets =================
__global__ void kprep(const float* __restrict__ inproj, const float* __restrict__ Wo,
                      const float* __restrict__ W1, const float* __restrict__ W2,
                      const int* __restrict__ curves)
{
    int i = blockIdx.x * 256 + threadIdx.x;
    if (i < 320*128) {
        int n = i >> 7, k = i & 127;
        float v = (n < DPROJ) ? inproj[(size_t)k*DPROJ + n] : 0.0f;
        Wp1[n*128 + kperm16(k)] = f2tf32(v);
    }
    if (i < 96*128) {
        int n = i >> 7, k = i & 127;
        WoP[n*128 + kperm16(k)] = f2tf32(Wo[(size_t)k*96 + n]);
    }
    if (i < 96*96) {
        int n = i / 96, k = i - n*96;
        W1P[n*96 + kperm16(k)] = f2tf32(W1[(size_t)k*96 + n]);
        W2P[n*96 + kperm16(k)] = f2tf32(W2[(size_t)k*96 + n]);
    }
    if (i < NTOK) {
        int b  = i / (TT*PP);
        int tp = i - b*TT*PP;
        int t  = tp / PP;
        int p  = tp - t*PP;
        Goff[i] = (b*TT + t)*PP + curves[b*PP + p];
    }
}

// smem float offsets for k012
#define OFF_US   0          /* u_s [64][140] = 8960 (cols 128..267 of u) */
#define OFF_ZS   8960       /* zs  [64][130] = 8320; As [64][128] overlay during GEMM */
#define OFF_DT   17280      /* dt[2][240] dA[2][240] = 960 */
#define OFF_BC   18240      /* [2][60] = 120 */
#define OFF_RMS  18360      /* [2][4][30] = 240 */
#define OFF_SCL  18600      /* [2][30] = 60 */
#define OFF_TOK  18660      /* [2][30] ints = 60 */
#define SM012_FLOATS 18720  /* 74880 B -> 3 CTAs/SM */

// ================= K012: prologue + in_proj GEMM + mamba =================
// CTA = (b, tg, qgrp): 60 tokens (3t x 20p); 256 threads; 3 CTAs/SM; grid 4096
__global__ void __launch_bounds__(256, 3) k012_fused(
    const float* __restrict__ x,
    const float* __restrict__ xstat,
    const float* __restrict__ xhres,
    const float* __restrict__ embed_w,
    const float* __restrict__ embed_b,
    const float* __restrict__ loan1_w,
    const float* __restrict__ loan1_b,
    const float* __restrict__ cw_f, const float* __restrict__ cb_f,
    const float* __restrict__ dtb_f, const float* __restrict__ al_f,
    const float* __restrict__ Dp_f, const float* __restrict__ nw_f,
    const float* __restrict__ cw_b, const float* __restrict__ cb_b,
    const float* __restrict__ dtb_b, const float* __restrict__ al_b,
    const float* __restrict__ Dp_b, const float* __restrict__ nw_b)
{
    extern __shared__ float smx[];
    float*    u_s  = smx + OFF_US;               // [64][140]
    float*    zs   = smx + OFF_ZS;               // [64][130]
    unsigned* As   = (unsigned*)(smx + OFF_ZS);  // [64][128] overlay (GEMM input)
    float*    dtA  = smx + OFF_DT;
    float*    BC   = smx + OFF_BC;
    float*    rmsp = smx + OFF_RMS;
    float*    scls = smx + OFF_SCL;
    int*      tokb = (int*)(smx + OFF_TOK);
    __shared__ float Aneg[2][8];

    const int blk  = blockIdx.x;
    const int b    = blk >> 11;
    const int tg   = (blk >> 10) & 1;
    const int qgrp = blk & 1023;
    const int tid  = threadIdx.x;
    const int warp = tid >> 5, lane = tid & 31;

    // ---- prologue: warp-per-token, 8 passes over 64 rows (60 real) ----
    #pragma unroll
    for (int pass = 0; pass < 8; pass++) {
        const int m = pass*8 + warp;
        if (m < 60) {
            const int t_loc = m / 20;
            const int p_loc = m - t_loc*20;
            const int gi = (b*TT + tg*3 + t_loc)*PP + qgrp*20 + p_loc;
            const size_t base = (size_t)Goff[gi];

            float hval = (lane < 28) ? xhres[base*28 + lane] : 0.0f;
            float sval = (lane < 8)  ? xstat[base*8 + lane]  : 0.0f;

            const int j0 = (lane >= 24) ? (lane - 24) * 4 : 0;
            float a0 = embed_b[j0], a1 = embed_b[j0+1], a2 = embed_b[j0+2], a3 = embed_b[j0+3];
            #pragma unroll
            for (int k = 0; k < 28; k++) {
                float hk = __shfl_sync(0xffffffffu, hval, k);
                a0 = fmaf(hk, embed_w[k*32 + j0    ], a0);
                a1 = fmaf(hk, embed_w[k*32 + j0 + 1], a1);
                a2 = fmaf(hk, embed_w[k*32 + j0 + 2], a2);
                a3 = fmaf(hk, embed_w[k*32 + j0 + 3], a3);
            }
            float v0, v1, v2, v3;
            if (lane < 24) {
                float4 xv = *(const float4*)(x + base*96 + lane*4);
                v0 = xv.x; v1 = xv.y; v2 = xv.z; v3 = xv.w;
            } else {
                v0 = tanhf(a0); v1 = tanhf(a1); v2 = tanhf(a2); v3 = tanhf(a3);
            }
            float s1 = v0+v1+v2+v3;
            float s2 = v0*v0+v1*v1+v2*v2+v3*v3;
            #pragma unroll
            for (int o = 16; o > 0; o >>= 1) {
                s1 += __shfl_xor_sync(0xffffffffu, s1, o);
                s2 += __shfl_xor_sync(0xffffffffu, s2, o);
            }
            float mu  = s1 * (1.0f/128.0f);
            float var = s2 * (1.0f/128.0f) - mu*mu;
            float rs  = rsqrtf(var + 1e-5f);
            float sv[8];
            #pragma unroll
            for (int k = 0; k < 8; k++) sv[k] = __shfl_sync(0xffffffffu, sval, k);
            const int c = lane*4;
            float o0 = loan1_b[c], o1 = loan1_b[c+1], o2 = loan1_b[c+2], o3 = loan1_b[c+3];
            #pragma unroll
            for (int k = 0; k < 8; k++) {
                o0 = fmaf(sv[k], loan1_w[k*128 + c    ], o0);
                o1 = fmaf(sv[k], loan1_w[k*128 + c + 1], o1);
                o2 = fmaf(sv[k], loan1_w[k*128 + c + 2], o2);
                o3 = fmaf(sv[k], loan1_w[k*128 + c + 3], o3);
            }
            o0 = (v0 - mu)*rs + tanhf(o0);
            o1 = (v1 - mu)*rs + tanhf(o1);
            o2 = (v2 - mu)*rs + tanhf(o2);
            o3 = (v3 - mu)*rs + tanhf(o3);
            stage4(As + m*128, (m&1)<<4, lane, o0, o1, o2, o3);
        } else {
            stage4(As + m*128, (m&1)<<4, lane, 0.f, 0.f, 0.f, 0.f);
        }
    }
    __syncthreads();

    // ---- GEMM: M=64, K=128; 8 warps (2m x 4n) ----
    const int gid = lane >> 2, tq = lane & 3;
    const int wm = warp & 1, wn = warp >> 1;
    float zacc[2][4][4] = {};      // chunk1 (z, cols 0..127), kept in registers
    {
        // chunk2: cols 128..287 -> u_s[.][col-128]
        float acc[2][5][4] = {};
        #pragma unroll
        for (int it = 0; it < 8; it++) {
            const int cb = it*16 + tq*4;
            uint4 a0v[2], a8v[2], bv[5];
            #pragma unroll
            for (int mt = 0; mt < 2; mt++) {
                int r0 = wm*32 + mt*16 + gid;
                int sw = (r0 & 1) << 4;
                a0v[mt] = *(const uint4*)(As + r0*128 + (cb ^ sw));
                a8v[mt] = *(const uint4*)(As + (r0+8)*128 + (cb ^ sw));
            }
            #pragma unroll
            for (int nt = 0; nt < 5; nt++) {
                int nr = 128 + wn*40 + nt*8 + gid;
                bv[nt] = *(const uint4*)(Wp1 + nr*128 + cb);
            }
            #pragma unroll
            for (int mt = 0; mt < 2; mt++) {
                #pragma unroll
                for (int nt = 0; nt < 5; nt++) {
                    unsigned aa1[4] = {a0v[mt].x, a8v[mt].x, a0v[mt].y, a8v[mt].y};
                    unsigned bb1[2] = {bv[nt].x, bv[nt].y};
                    mma_tf32(acc[mt][nt], aa1, bb1);
                    unsigned aa2[4] = {a0v[mt].z, a8v[mt].z, a0v[mt].w, a8v[mt].w};
                    unsigned bb2[2] = {bv[nt].z, bv[nt].w};
                    mma_tf32(acc[mt][nt], aa2, bb2);
                }
            }
        }
        #pragma unroll
        for (int mt = 0; mt < 2; mt++) {
            int row = wm*32 + mt*16 + gid;
            #pragma unroll
            for (int nt = 0; nt < 5; nt++) {
                int col = 128 + wn*40 + nt*8 + tq*2;
                if (col < DPROJ) {
                    *(float2*)(u_s + row*140 + col - 128) =
                        make_float2(acc[mt][nt][0], acc[mt][nt][1]);
                    *(float2*)(u_s + (row+8)*140 + col - 128) =
                        make_float2(acc[mt][nt][2], acc[mt][nt][3]);
                }
            }
        }
        // chunk1: z = cols 0..127, accumulate into zacc (registers)
        #pragma unroll
        for (int it = 0; it < 8; it++) {
            const int cb = it*16 + tq*4;
            uint4 a0v[2], a8v[2], bv[4];
            #pragma unroll
            for (int mt = 0; mt < 2; mt++) {
                int r0 = wm*32 + mt*16 + gid;
                int sw = (r0 & 1) << 4;
                a0v[mt] = *(const uint4*)(As + r0*128 + (cb ^ sw));
                a8v[mt] = *(const uint4*)(As + (r0+8)*128 + (cb ^ sw));
            }
            #pragma unroll
            for (int nt = 0; nt < 4; nt++) {
                int nr = wn*32 + nt*8 + gid;
                bv[nt] = *(const uint4*)(Wp1 + nr*128 + cb);
            }
            #pragma unroll
            for (int mt = 0; mt < 2; mt++) {
                #pragma unroll
                for (int nt = 0; nt < 4; nt++) {
                    unsigned aa1[4] = {a0v[mt].x, a8v[mt].x, a0v[mt].y, a8v[mt].y};
                    unsigned bb1[2] = {bv[nt].x, bv[nt].y};
                    mma_tf32(zacc[mt][nt], aa1, bb1);
                    unsigned aa2[4] = {a0v[mt].z, a8v[mt].z, a0v[mt].w, a8v[mt].w};
                    unsigned bb2[2] = {bv[nt].z, bv[nt].w};
                    mma_tf32(zacc[mt][nt], aa2, bb2);
                }
            }
        }
    }
    if (tid < 16) Aneg[tid>>3][tid&7] = -expf((tid < 8 ? al_f : al_b)[tid & 7]);
    __syncthreads();   // all As reads done -> zs overlay is safe

    // write z registers into zs [64][130]
    #pragma unroll
    for (int mt = 0; mt < 2; mt++) {
        int row = wm*32 + mt*16 + gid;
        #pragma unroll
        for (int nt = 0; nt < 4; nt++) {
            int col = wn*32 + nt*8 + tq*2;
            *(float2*)(zs + row*130 + col)     = make_float2(zacc[mt][nt][0], zacc[mt][nt][1]);
            *(float2*)(zs + (row+8)*130 + col) = make_float2(zacc[mt][nt][2], zacc[mt][nt][3]);
        }
    }

    // ---- mamba: 2 rounds (r = direction); group g = seq (qg = qgrp*2+g) ----
    const int g  = tid >> 7;
    const int lt = tid & 127;
    float* dts = dtA + g*240;
    float* dAs = dtA + 480 + g*240;
    const int qg_src = qgrp*2 + g;
    const int wig = warp & 3;

    #pragma unroll
    for (int r = 0; r < 2; r++) {
        const float* conv_w = r ? cw_b  : cw_f;
        const float* conv_b = r ? cb_b  : cb_f;
        const float* dtbp   = r ? dtb_b : dtb_f;
        const float* Dpp    = r ? Dp_b  : Dp_f;

        // dt/dA (raw dt at u_s col 130+h)
        for (int i = lt; i < 240; i += 128) {
            int l = i >> 3, h = i & 7;
            int l10 = l / 10, lr = l - l10*10;
            int mu_ = l10*20 + g*10 + (r ? (9 - lr) : lr);
            float raw = u_s[mu_*140 + 130 + h] + dtbp[h];
            float dt = (raw > 20.f) ? raw : log1pf(expf(raw));
            dts[l*8 + h] = dt;
            dAs[l*8 + h] = expf(dt * Aneg[r][h]);
        }
        // conv+silu own channel (c = lt) -> registers
        float xreg[30];
        {
            const int c = lt;
            float w0 = conv_w[c*3+0], w1 = conv_w[c*3+1], w2 = conv_w[c*3+2];
            float bias = conv_b[c];
            float p2 = 0.f, p1 = 0.f;
            #pragma unroll
            for (int l = 0; l < 30; l++) {
                int l10 = l / 10, lr = l - l10*10;
                int mu_ = l10*20 + g*10 + (r ? (9 - lr) : lr);
                float v = u_s[mu_*140 + c];
                float a = fmaf(p2, w0, fmaf(p1, w1, fmaf(v, w2, bias)));
                xreg[l] = a / (1.f + expf(-a));
                p2 = p1; p1 = v;
            }
        }
        // conv for B (128) / C (129) channels by threads 0,1 of group
        if (lt < 2) {
            const int c2 = 128 + lt;
            float w0 = conv_w[c2*3+0], w1 = conv_w[c2*3+1], w2 = conv_w[c2*3+2];
            float bias = conv_b[c2];
            float p2 = 0.f, p1 = 0.f;
            #pragma unroll
            for (int l = 0; l < 30; l++) {
                int l10 = l / 10, lr = l - l10*10;
                int mu_ = l10*20 + g*10 + (r ? (9 - lr) : lr);
                float v = u_s[mu_*140 + c2];
                float a = fmaf(p2, w0, fmaf(p1, w1, fmaf(v, w2, bias)));
                BC[g*60 + l*2 + lt] = a / (1.f + expf(-a));
                p2 = p1; p1 = v;
            }
        }
        __syncthreads();   // BC + dts/dAs visible (also zs on first round)

        // scalar scan in registers; gate z from zs
        {
            const int c = lt, h = c >> 4;
            const float Dh = Dpp[h];
            float hs = 0.f;
            #pragma unroll
            for (int l = 0; l < 30; l++) {
                int l10 = l / 10, lr = l - l10*10;
                int mu_ = l10*20 + g*10 + (r ? (9 - lr) : lr);
                float xv = xreg[l];
                float Bv = BC[g*60 + l*2];
                float Cv = BC[g*60 + l*2 + 1];
                hs = fmaf(hs, dAs[l*8+h], dts[l*8+h]*xv*Bv);
                float y = fmaf(hs, Cv, xv*Dh);
                float z = zs[mu_*130 + c];
                y *= z / (1.f + expf(-z));
                xreg[l] = y;
            }
        }
        // RMS: warp partials
        #pragma unroll
        for (int l = 0; l < 30; l++) {
            float ss = xreg[l]*xreg[l];
            #pragma unroll
            for (int o = 16; o > 0; o >>= 1) ss += __shfl_xor_sync(0xffffffffu, ss, o);
            if (lane == 0) rmsp[(g*4 + wig)*30 + l] = ss;
        }
        __syncthreads();
        // warp 0 of each group: scales + token bases
        if (wig == 0 && lane < 30) {
            int l = lane;
            float ss = rmsp[(g*4+0)*30 + l] + rmsp[(g*4+1)*30 + l]
                     + rmsp[(g*4+2)*30 + l] + rmsp[(g*4+3)*30 + l];
            scls[g*30 + l] = rsqrtf(ss*(1.f/128.f) + 1e-5f) * 0.5f;
            const int qgu = r ? (2047 - qg_src) : qg_src;
            const int abase = (tg*1024 + (qgu>>1))*6 + (qgu&1);
            int l3 = l / 3;
            int f = l3*12288 + abase + (l - l3*3)*2;
            int t_out = f / PP;
            int p_out = f - t_out*PP;
            if (r) p_out = PP-1 - p_out;
            tokb[g*30 + l] = (b*TT + t_out)*PP + p_out;
        }
        __syncthreads();
        // write y (coalesced 128B per warp per l)
        {
            const float* nww = r ? nw_b : nw_f;
            float* ybuf = r ? S_yb : S_yf;
            const float nwc = nww[lt];
            #pragma unroll
            for (int l = 0; l < 30; l++) {
                ybuf[(size_t)tokb[g*30 + l]*128 + lt] = xreg[l]*scls[g*30 + l]*nwc;
            }
        }
    }
}

// ===== GEMM helper: M64xN96, A in smem, B via LDG =====
template<int KIT, int KSTRIDE>
__device__ __forceinline__ void gemm_ldgB(const unsigned* __restrict__ Ab, int SA,
                                          const unsigned* __restrict__ Wg,
                                          int wm, int wn, int gid, int tq,
                                          float (&acc)[2][3][4])
{
    #pragma unroll
    for (int it = 0; it < KIT; it++) {
        const int cb = it*16 + tq*4;
        uint4 a0v[2], a8v[2], bv[3];
        #pragma unroll
        for (int mt = 0; mt < 2; mt++) {
            int r0 = wm*32 + mt*16 + gid;
            int sw = (r0 & 1) << 4;
            a0v[mt] = *(const uint4*)(Ab + r0*SA + (cb ^ sw));
            a8v[mt] = *(const uint4*)(Ab + (r0+8)*SA + (cb ^ sw));
        }
        #pragma unroll
        for (int nt = 0; nt < 3; nt++) {
            int nr = wn*24 + nt*8 + gid;
            bv[nt] = *(const uint4*)(Wg + nr*KSTRIDE + cb);
        }
        #pragma unroll
        for (int mt = 0; mt < 2; mt++) {
            #pragma unroll
            for (int nt = 0; nt < 3; nt++) {
                unsigned aa1[4] = {a0v[mt].x, a8v[mt].x, a0v[mt].y, a8v[mt].y};
                unsigned bb1[2] = {bv[nt].x, bv[nt].y};
                mma_tf32(acc[mt][nt], aa1, bb1);
                unsigned aa2[4] = {a0v[mt].z, a8v[mt].z, a0v[mt].w, a8v[mt].w};
                unsigned bb2[2] = {bv[nt].z, bv[nt].w};
                mma_tf32(acc[mt][nt], aa2, bb2);
            }
        }
    }
}

// ================= K34: out_proj + residual + LN + loan2 + MLP, fused (R5) ==========
__global__ void __launch_bounds__(256, 3) k34_fused(
    const float* __restrict__ x,
    const float* __restrict__ xstat,
    const float* __restrict__ loan2_w,
    const float* __restrict__ loan2_b,
    const float* __restrict__ b1,
    const float* __restrict__ b2,
    float* __restrict__ out)
{
    extern __shared__ unsigned smf[];
    unsigned* As  = smf;                     // [64][128]; tts/hs overlay
    float*    x1s = (float*)(smf + 64*128);  // [64][100]
    unsigned* tts = As;
    unsigned* hs  = As;

    const int tid = threadIdx.x;
    const int m_base = blockIdx.x * 64;
    const int warp = tid >> 5, lane = tid & 31;
    const int gid = lane >> 2, tq = lane & 3;
    const int wm = warp & 1, wn = warp >> 1;

    for (int i = tid; i < 64*32; i += 256) {
        int m = i >> 5, c = i & 31;
        size_t off = (size_t)(m_base+m)*128 + c*4;
        float4 a = *(const float4*)(S_yf + off);
        float4 q = *(const float4*)(S_yb + off);
        stage4(As + m*128, (m&1)<<4, c, a.x+q.x, a.y+q.y, a.z+q.z, a.w+q.w);
    }
    __syncthreads();

    float acc[2][3][4] = {};
    gemm_ldgB<8,128>(As, 128, WoP, wm, wn, gid, tq, acc);

    #pragma unroll
    for (int mt = 0; mt < 2; mt++) {
        int r = wm*32 + mt*16 + gid;
        #pragma unroll
        for (int nt = 0; nt < 3; nt++) {
            int c = wn*24 + nt*8 + tq*2;
            x1s[r*100 + c]     = acc[mt][nt][0];
            x1s[r*100 + c + 1] = acc[mt][nt][1];
            x1s[(r+8)*100 + c]     = acc[mt][nt][2];
            x1s[(r+8)*100 + c + 1] = acc[mt][nt][3];
        }
    }
    __syncthreads();

    for (int r = warp; r < 64; r += 8) {
        int gm = m_base + r;
        size_t base = (size_t)Goff[gm];
        size_t xb = base*96;
        float v0 = x1s[r*100 + lane*3 + 0] + x[xb + lane*3 + 0];
        float v1 = x1s[r*100 + lane*3 + 1] + x[xb + lane*3 + 1];
        float v2 = x1s[r*100 + lane*3 + 2] + x[xb + lane*3 + 2];
        x1s[r*100 + lane*3 + 0] = v0;
        x1s[r*100 + lane*3 + 1] = v1;
        x1s[r*100 + lane*3 + 2] = v2;
        float s1 = v0+v1+v2, s2 = v0*v0+v1*v1+v2*v2;
        #pragma unroll
        for (int o = 16; o > 0; o >>= 1) {
            s1 += __shfl_xor_sync(0xffffffffu, s1, o);
            s2 += __shfl_xor_sync(0xffffffffu, s2, o);
        }
        float mu  = s1 * (1.0f/96.0f);
        float var = s2 * (1.0f/96.0f) - mu*mu;
        float rs  = rsqrtf(var + 1e-5f);
        size_t sbase = base*8;
        float xs[8];
        #pragma unroll
        for (int k = 0; k < 8; k++) xs[k] = xstat[sbase + k];
        int swr = (r & 1) << 4;
        #pragma unroll
        for (int i2 = 0; i2 < 3; i2++) {
            int jj = lane*3 + i2;
            float a = loan2_b[jj];
            #pragma unroll
            for (int k = 0; k < 8; k++) a = fmaf(xs[k], loan2_w[k*96 + jj], a);
            float vv = (i2 == 0) ? v0 : ((i2 == 1) ? v1 : v2);
            tts[r*96 + (kperm16(jj) ^ swr)] = f2tf32((vv - mu)*rs + tanhf(a));
        }
    }
    __syncthreads();

    float acc1[2][3][4] = {};
    gemm_ldgB<6,96>(tts, 96, W1P, wm, wn, gid, tq, acc1);
    __syncthreads();

    #pragma unroll
    for (int mt = 0; mt < 2; mt++) {
        int r = wm*32 + mt*16 + gid;
        int swr = (r & 1) << 4;
        #pragma unroll
        for (int nt = 0; nt < 3; nt++) {
            int c = wn*24 + nt*8 + tq*2;
            float bb0 = b1[c], bb1 = b1[c+1];
            hs[r*96 + (kperm16(c)   ^ swr)] = f2tf32(geluf(acc1[mt][nt][0] + bb0));
            hs[r*96 + (kperm16(c+1) ^ swr)] = f2tf32(geluf(acc1[mt][nt][1] + bb1));
            hs[(r+8)*96 + (kperm16(c)   ^ swr)] = f2tf32(geluf(acc1[mt][nt][2] + bb0));
            hs[(r+8)*96 + (kperm16(c+1) ^ swr)] = f2tf32(geluf(acc1[mt][nt][3] + bb1));
        }
    }
    __syncthreads();

    float acc2[2][3][4] = {};
    gemm_ldgB<6,96>(hs, 96, W2P, wm, wn, gid, tq, acc2);

    #pragma unroll
    for (int mt = 0; mt < 2; mt++) {
        int r = wm*32 + mt*16 + gid;
        int gm0 = m_base + r, gm8 = gm0 + 8;
        #pragma unroll
        for (int nt = 0; nt < 3; nt++) {
            int c = wn*24 + nt*8 + tq*2;
            float bb0 = b2[c], bb1 = b2[c+1];
            *(float2*)(out + (size_t)gm0*96 + c) = make_float2(
                acc2[mt][nt][0] + bb0 + x1s[r*100 + c],
                acc2[mt][nt][1] + bb1 + x1s[r*100 + c + 1]);
            *(float2*)(out + (size_t)gm8*96 + c) = make_float2(
                acc2[mt][nt][2] + bb0 + x1s[(r+8)*100 + c],
                acc2[mt][nt][3] + bb1 + x1s[(r+8)*100 + c + 1]);
        }
    }
}

// ================= launcher =================
extern "C" void kernel_launch(void* const* d_in, const int* in_sizes, int n_in,
                              void* d_out, int out_size)
{
    const float* x       = (const float*)d_in[0];
    const float* xstat   = (const float*)d_in[1];
    const float* xhres   = (const float*)d_in[2];
    const int*   curves  = (const int*)  d_in[3];
    const float* embed_w = (const float*)d_in[4];
    const float* embed_b = (const float*)d_in[5];
    const float* loan1_w = (const float*)d_in[6];
    const float* loan1_b = (const float*)d_in[7];
    const float* loan2_w = (const float*)d_in[8];
    const float* loan2_b = (const float*)d_in[9];
    const float* in_proj = (const float*)d_in[10];
    const float* cw_f  = (const float*)d_in[11];
    const float* cb_f  = (const float*)d_in[12];
    const float* dtb_f = (const float*)d_in[13];
    const float* al_f  = (const float*)d_in[14];
    const float* Dp_f  = (const float*)d_in[15];
    const float* nw_f  = (const float*)d_in[16];
    const float* cw_b  = (const float*)d_in[17];
    const float* cb_b  = (const float*)d_in[18];
    const float* dtb_b = (const float*)d_in[19];
    const float* al_b  = (const float*)d_in[20];
    const float* Dp_b  = (const float*)d_in[21];
    const float* nw_b  = (const float*)d_in[22];
    const float* Wo    = (const float*)d_in[23];
    const float* W1    = (const float*)d_in[24];
    const float* b1    = (const float*)d_in[25];
    const float* W2    = (const float*)d_in[26];
    const float* b2    = (const float*)d_in[27];
    float* out = (float*)d_out;

    const int smem012 = SM012_FLOATS * 4;        // 74880 -> 3 CTAs/SM
    const int smem34  = (64*128 + 64*100) * 4;   // 58368

    cudaFuncSetAttribute(k012_fused, cudaFuncAttributeMaxDynamicSharedMemorySize, smem012);
    cudaFuncSetAttribute(k34_fused,  cudaFuncAttributeMaxDynamicSharedMemorySize, smem34);

    kprep<<<NTOK/256, 256>>>(in_proj, Wo, W1, W2, curves);

    k012_fused<<<4096, 256, smem012>>>(x, xstat, xhres,
                                       embed_w, embed_b, loan1_w, loan1_b,
                                       cw_f, cb_f, dtb_f, al_f, Dp_f, nw_f,
                                       cw_b, cb_b, dtb_b, al_b, Dp_b, nw_b);

    k34_fused<<<NTOK/64, 256, smem34>>>(x, xstat, loan2_w, loan2_b, b1, b2, out);
}

// round 10
// speedup vs baseline: 1.3237x; 1.3237x over previous
#include <cuda_runtime.h>
#include <math.h>

#define BB 2
#define TT 6
#define PP 20480
#define NTOK (BB*TT*PP)      /* 245760 */
#define DPROJ 266

// ---------------- scratch ----------------
__device__ float S_yf[(size_t)NTOK*128];
__device__ float S_yb[(size_t)NTOK*128];
__device__ int   Goff[NTOK];
// pre-permuted tf32 weights (B operands, n-major, kperm16'd)
__device__ unsigned Wp1[320*128];
__device__ unsigned WoP[96*128];
__device__ unsigned W1P[96*96];
__device__ unsigned W2P[96*96];

__device__ __forceinline__ float geluf(float v) {
    return 0.5f * v * (1.0f + erff(v * 0.70710678118654752f));
}
__device__ __forceinline__ unsigned f2tf32(float f) {
    unsigned r;
    asm("cvt.rna.tf32.f32 %0, %1;" : "=r"(r) : "f"(f));
    return r;
}
__device__ __forceinline__ int kperm16(int k) {
    int g = k & ~15, j = k & 15;
    return g + ((j & 3) << 2) + (j >> 2);
}
__device__ __forceinline__ void mma_tf32(float* c, const unsigned* a, const unsigned* b) {
    asm volatile(
        "mma.sync.aligned.m16n8k8.row.col.f32.tf32.tf32.f32 "
        "{%0,%1,%2,%3}, {%4,%5,%6,%7}, {%8,%9}, {%0,%1,%2,%3};"
        : "+f"(c[0]), "+f"(c[1]), "+f"(c[2]), "+f"(c[3])
        : "r"(a[0]), "r"(a[1]), "r"(a[2]), "r"(a[3]), "r"(b[0]), "r"(b[1]));
}
__device__ __forceinline__ void stage4(unsigned* row, int sw, int c, float x, float y, float z, float w) {
    int g = (c >> 2) << 4, r = c & 3;
    row[(g + r     ) ^ sw] = f2tf32(x);
    row[(g + r + 4 ) ^ sw] = f2tf32(y);
    row[(g + r + 8 ) ^ sw] = f2tf32(z);
    row[(g + r + 12) ^ sw] = f2tf32(w);
}

// ================= prep: weights + gather offsets =================
__global__ void kprep(const float* __restrict__ inproj, const float* __restrict__ Wo,
                      const float* __restrict__ W1, const float* __restrict__ W2,
                      const int* __restrict__ curves)
{
    int i = blockIdx.x * 256 + threadIdx.x;
    if (i < 320*128) {
        int n = i >> 7, k = i & 127;
        float v = (n < DPROJ) ? inproj[(size_t)k*DPROJ + n] : 0.0f;
        Wp1[n*128 + kperm16(k)] = f2tf32(v);
    }
    if (i < 96*128) {
        int n = i >> 7, k = i & 127;
        WoP[n*128 + kperm16(k)] = f2tf32(Wo[(size_t)k*96 + n]);
    }
    if (i < 96*96) {
        int n = i / 96, k = i - n*96;
        W1P[n*96 + kperm16(k)] = f2tf32(W1[(size_t)k*96 + n]);
        W2P[n*96 + kperm16(k)] = f2tf32(W2[(size_t)k*96 + n]);
    }
    if (i < NTOK) {
        int b  = i / (TT*PP);
        int tp = i - b*TT*PP;
        int t  = tp / PP;
        int p  = tp - t*PP;
        Goff[i] = (b*TT + t)*PP + curves[b*PP + p];
    }
}

// ================= K012: prologue + in_proj GEMM + mamba (R5, verified 970us) =====
// CTA = (b, tg, qgrp): 60 tokens (3 t x 20 p), GEMM in smem, 2 fwd + 2 bwd scans.
// 256 threads, 2 CTAs/SM. Grid = 4096.
__global__ void __launch_bounds__(256, 2) k012_fused(
    const float* __restrict__ x,
    const float* __restrict__ xstat,
    const float* __restrict__ xhres,
    const float* __restrict__ embed_w,
    const float* __restrict__ embed_b,
    const float* __restrict__ loan1_w,
    const float* __restrict__ loan1_b,
    const float* __restrict__ cw_f, const float* __restrict__ cb_f,
    const float* __restrict__ dtb_f, const float* __restrict__ al_f,
    const float* __restrict__ Dp_f, const float* __restrict__ nw_f,
    const float* __restrict__ cw_b, const float* __restrict__ cb_b,
    const float* __restrict__ dtb_b, const float* __restrict__ al_b,
    const float* __restrict__ Dp_b, const float* __restrict__ nw_b)
{
    extern __shared__ float smx[];
    float*    u_s = smx;                     // [64][268] fp32
    float*    ovl = smx + 64*268;            // overlay: As (GEMM) then xc0/xc1
    unsigned* As  = (unsigned*)ovl;          // [64][128] swizzled tf32
    float*    dtA = smx + 64*268 + 64*128;   // dt[2][240] dA[2][240]
    __shared__ float Aneg[2][8];

    const int blk  = blockIdx.x;
    const int b    = blk >> 11;
    const int tg   = (blk >> 10) & 1;
    const int qgrp = blk & 1023;
    const int tid  = threadIdx.x;
    const int warp = tid >> 5, lane = tid & 31;

    // ---- prologue: warp-per-token, 8 passes over 64 rows (60 real) ----
    for (int pass = 0; pass < 8; pass++) {
        const int m = pass*8 + warp;
        if (m < 60) {
            const int t_loc = m / 20;
            const int p_loc = m - t_loc*20;
            const int gi = (b*TT + tg*3 + t_loc)*PP + qgrp*20 + p_loc;
            const size_t base = (size_t)Goff[gi];

            float hval = (lane < 28) ? xhres[base*28 + lane] : 0.0f;
            float sval = (lane < 8)  ? xstat[base*8 + lane]  : 0.0f;

            const int j0 = (lane >= 24) ? (lane - 24) * 4 : 0;
            float a0 = embed_b[j0], a1 = embed_b[j0+1], a2 = embed_b[j0+2], a3 = embed_b[j0+3];
            #pragma unroll
            for (int k = 0; k < 28; k++) {
                float hk = __shfl_sync(0xffffffffu, hval, k);
                a0 = fmaf(hk, embed_w[k*32 + j0    ], a0);
                a1 = fmaf(hk, embed_w[k*32 + j0 + 1], a1);
                a2 = fmaf(hk, embed_w[k*32 + j0 + 2], a2);
                a3 = fmaf(hk, embed_w[k*32 + j0 + 3], a3);
            }
            float v0, v1, v2, v3;
            if (lane < 24) {
                float4 xv = *(const float4*)(x + base*96 + lane*4);
                v0 = xv.x; v1 = xv.y; v2 = xv.z; v3 = xv.w;
            } else {
                v0 = tanhf(a0); v1 = tanhf(a1); v2 = tanhf(a2); v3 = tanhf(a3);
            }
            float s1 = v0+v1+v2+v3;
            float s2 = v0*v0+v1*v1+v2*v2+v3*v3;
            #pragma unroll
            for (int o = 16; o > 0; o >>= 1) {
                s1 += __shfl_xor_sync(0xffffffffu, s1, o);
                s2 += __shfl_xor_sync(0xffffffffu, s2, o);
            }
            float mu  = s1 * (1.0f/128.0f);
            float var = s2 * (1.0f/128.0f) - mu*mu;
            float rs  = rsqrtf(var + 1e-5f);
            float sv[8];
            #pragma unroll
            for (int k = 0; k < 8; k++) sv[k] = __shfl_sync(0xffffffffu, sval, k);
            const int c = lane*4;
            float o0 = loan1_b[c], o1 = loan1_b[c+1], o2 = loan1_b[c+2], o3 = loan1_b[c+3];
            #pragma unroll
            for (int k = 0; k < 8; k++) {
                o0 = fmaf(sv[k], loan1_w[k*128 + c    ], o0);
                o1 = fmaf(sv[k], loan1_w[k*128 + c + 1], o1);
                o2 = fmaf(sv[k], loan1_w[k*128 + c + 2], o2);
                o3 = fmaf(sv[k], loan1_w[k*128 + c + 3], o3);
            }
            o0 = (v0 - mu)*rs + tanhf(o0);
            o1 = (v1 - mu)*rs + tanhf(o1);
            o2 = (v2 - mu)*rs + tanhf(o2);
            o3 = (v3 - mu)*rs + tanhf(o3);
            stage4(As + m*128, (m&1)<<4, lane, o0, o1, o2, o3);
        } else {
            stage4(As + m*128, (m&1)<<4, lane, 0.f, 0.f, 0.f, 0.f);
        }
    }
    __syncthreads();

    // ---- GEMM: u = xn @ Wp1, M=64, N=320 (2 chunks of 160), K=128, into u_s ----
    {
        const int gid = lane >> 2, tq = lane & 3;
        const int wm = warp & 1, wn = warp >> 1;
        #pragma unroll
        for (int nc = 0; nc < 2; nc++) {
            float acc[2][5][4] = {};
            #pragma unroll
            for (int it = 0; it < 8; it++) {
                const int cb = it*16 + tq*4;
                uint4 a0v[2], a8v[2], bv[5];
                #pragma unroll
                for (int mt = 0; mt < 2; mt++) {
                    int r0 = wm*32 + mt*16 + gid;
                    int sw = (r0 & 1) << 4;
                    a0v[mt] = *(const uint4*)(As + r0*128 + (cb ^ sw));
                    a8v[mt] = *(const uint4*)(As + (r0+8)*128 + (cb ^ sw));
                }
                #pragma unroll
                for (int nt = 0; nt < 5; nt++) {
                    int nr = nc*160 + wn*40 + nt*8 + gid;
                    bv[nt] = *(const uint4*)(Wp1 + nr*128 + cb);
                }
                #pragma unroll
                for (int mt = 0; mt < 2; mt++) {
                    #pragma unroll
                    for (int nt = 0; nt < 5; nt++) {
                        unsigned aa1[4] = {a0v[mt].x, a8v[mt].x, a0v[mt].y, a8v[mt].y};
                        unsigned bb1[2] = {bv[nt].x, bv[nt].y};
                        mma_tf32(acc[mt][nt], aa1, bb1);
                        unsigned aa2[4] = {a0v[mt].z, a8v[mt].z, a0v[mt].w, a8v[mt].w};
                        unsigned bb2[2] = {bv[nt].z, bv[nt].w};
                        mma_tf32(acc[mt][nt], aa2, bb2);
                    }
                }
            }
            #pragma unroll
            for (int mt = 0; mt < 2; mt++) {
                int row = wm*32 + mt*16 + gid;
                #pragma unroll
                for (int nt = 0; nt < 5; nt++) {
                    int col = nc*160 + wn*40 + nt*8 + tq*2;
                    if (col < DPROJ) {
                        *(float2*)(u_s + row*268 + col) =
                            make_float2(acc[mt][nt][0], acc[mt][nt][1]);
                        *(float2*)(u_s + (row+8)*268 + col) =
                            make_float2(acc[mt][nt][2], acc[mt][nt][3]);
                    }
                }
            }
        }
    }
    if (tid < 16) Aneg[tid>>3][tid&7] = -expf((tid < 8 ? al_f : al_b)[tid & 7]);
    __syncthreads();   // u_s complete; As region free -> xc overlay

    // ---- mamba: 2 rounds (fwd, bwd); group g = seq (qg = qgrp*2+g) ----
    const int g  = tid >> 7;
    const int lt = tid & 127;
    float* xcg = ovl + g*3960;           // [30][132]
    float* dts = dtA + g*240;
    float* dAs = dtA + 480 + g*240;
    const int qg_src = qgrp*2 + g;

    #pragma unroll
    for (int r = 0; r < 2; r++) {
        const float* conv_w = r ? cw_b  : cw_f;
        const float* conv_b = r ? cb_b  : cb_f;
        const float* dtbp   = r ? dtb_b : dtb_f;
        const float* Dpp    = r ? Dp_b  : Dp_f;

        for (int i = lt; i < 240; i += 128) {
            int l = i >> 3, h = i & 7;
            int l10 = l / 10, lr = l - l10*10;
            int lu_r = r ? (9 - lr) : lr;
            int mu_ = l10*20 + g*10 + lu_r;
            float raw = u_s[mu_*268 + 258 + h] + dtbp[h];
            float dt = (raw > 20.f) ? raw : log1pf(expf(raw));
            dts[l*8 + h] = dt;
            dAs[l*8 + h] = expf(dt * Aneg[r][h]);
        }
        for (int c = lt; c < 130; c += 128) {
            float w0 = conv_w[c*3+0], w1 = conv_w[c*3+1], w2 = conv_w[c*3+2];
            float bias = conv_b[c];
            float p2 = 0.f, p1 = 0.f;
            #pragma unroll
            for (int l = 0; l < 30; l++) {
                int l10 = l / 10, lr = l - l10*10;
                int mu_ = l10*20 + g*10 + (r ? (9 - lr) : lr);
                float v = u_s[mu_*268 + 128 + c];
                float a = fmaf(p2, w0, fmaf(p1, w1, fmaf(v, w2, bias)));
                xcg[l*132 + c] = a / (1.f + expf(-a));
                p2 = p1; p1 = v;
            }
        }
        __syncthreads();

        {
            const int c = lt, h = c >> 4;
            const float Dh = Dpp[h];
            float hs = 0.f;
            #pragma unroll
            for (int l = 0; l < 30; l++) {
                int l10 = l / 10, lr = l - l10*10;
                int mu_ = l10*20 + g*10 + (r ? (9 - lr) : lr);
                float xv = xcg[l*132 + c];
                float Bv = xcg[l*132 + 128];
                float Cv = xcg[l*132 + 129];
                hs = fmaf(hs, dAs[l*8+h], dts[l*8+h]*xv*Bv);
                float y = fmaf(hs, Cv, xv*Dh);
                float z = u_s[mu_*268 + c];
                y *= z / (1.f + expf(-z));
                xcg[l*132 + c] = y;
            }
        }
        __syncthreads();

        {
            const int w4 = warp & 3;
            const float* nww = r ? nw_b : nw_f;
            float* ybuf = r ? S_yb : S_yf;
            const int qgu = r ? (2047 - qg_src) : qg_src;
            const int abase = (tg*1024 + (qgu>>1))*6 + (qgu&1);
            for (int l = w4; l < 30; l += 4) {
                float4 v = *(float4*)(xcg + l*132 + lane*4);
                float ss = v.x*v.x + v.y*v.y + v.z*v.z + v.w*v.w;
                #pragma unroll
                for (int o = 16; o > 0; o >>= 1) ss += __shfl_xor_sync(0xffffffffu, ss, o);
                float scale = rsqrtf(ss*(1.f/128.f) + 1e-5f) * 0.5f;
                int l3 = l / 3;
                int f = l3*12288 + abase + (l - l3*3)*2;
                int t_out = f / PP;
                int p_out = f - t_out*PP;
                if (r) p_out = PP-1 - p_out;
                float4 w = *(const float4*)(nww + lane*4);
                float4 o;
                o.x = v.x*scale*w.x; o.y = v.y*scale*w.y;
                o.z = v.z*scale*w.z; o.w = v.w*scale*w.w;
                *(float4*)(ybuf + ((size_t)(b*TT + t_out)*PP + p_out)*128 + lane*4) = o;
            }
        }
        __syncthreads();
    }
}

// ===== GEMM helper: M64xN96, A in smem, B via LDG =====
template<int KIT, int KSTRIDE>
__device__ __forceinline__ void gemm_ldgB(const unsigned* __restrict__ Ab, int SA,
                                          const unsigned* __restrict__ Wg,
                                          int wm, int wn, int gid, int tq,
                                          float (&acc)[2][3][4])
{
    #pragma unroll
    for (int it = 0; it < KIT; it++) {
        const int cb = it*16 + tq*4;
        uint4 a0v[2], a8v[2], bv[3];
        #pragma unroll
        for (int mt = 0; mt < 2; mt++) {
            int r0 = wm*32 + mt*16 + gid;
            int sw = (r0 & 1) << 4;
            a0v[mt] = *(const uint4*)(Ab + r0*SA + (cb ^ sw));
            a8v[mt] = *(const uint4*)(Ab + (r0+8)*SA + (cb ^ sw));
        }
        #pragma unroll
        for (int nt = 0; nt < 3; nt++) {
            int nr = wn*24 + nt*8 + gid;
            bv[nt] = *(const uint4*)(Wg + nr*KSTRIDE + cb);
        }
        #pragma unroll
        for (int mt = 0; mt < 2; mt++) {
            #pragma unroll
            for (int nt = 0; nt < 3; nt++) {
                unsigned aa1[4] = {a0v[mt].x, a8v[mt].x, a0v[mt].y, a8v[mt].y};
                unsigned bb1[2] = {bv[nt].x, bv[nt].y};
                mma_tf32(acc[mt][nt], aa1, bb1);
                unsigned aa2[4] = {a0v[mt].z, a8v[mt].z, a0v[mt].w, a8v[mt].w};
                unsigned bb2[2] = {bv[nt].z, bv[nt].w};
                mma_tf32(acc[mt][nt], aa2, bb2);
            }
        }
    }
}

// ================= K34: out_proj + residual + LN + loan2 + MLP, fused ==========
// R5 shape + loan2 smem staging + hoisted kperm indices
__global__ void __launch_bounds__(256, 3) k34_fused(
    const float* __restrict__ x,
    const float* __restrict__ xstat,
    const float* __restrict__ loan2_w,
    const float* __restrict__ loan2_b,
    const float* __restrict__ b1,
    const float* __restrict__ b2,
    float* __restrict__ out)
{
    extern __shared__ unsigned smf[];
    unsigned* As  = smf;                     // [64][128]; tts/hs overlay
    float*    x1s = (float*)(smf + 64*128);  // [64][100]
    float*    ls2 = (float*)(smf + 64*128 + 64*100);        // [8][96] loan2_w
    float*    lb2 = (float*)(smf + 64*128 + 64*100 + 768);  // [96] loan2_b
    unsigned* tts = As;
    unsigned* hs  = As;

    const int tid = threadIdx.x;
    const int m_base = blockIdx.x * 64;
    const int warp = tid >> 5, lane = tid & 31;
    const int gid = lane >> 2, tq = lane & 3;
    const int wm = warp & 1, wn = warp >> 1;

    // stage loan2 weights into smem (once)
    for (int i = tid; i < 768; i += 256) ls2[i] = loan2_w[i];
    if (tid < 96) lb2[tid] = loan2_b[tid];

    for (int i = tid; i < 64*32; i += 256) {
        int m = i >> 5, c = i & 31;
        size_t off = (size_t)(m_base+m)*128 + c*4;
        float4 a = *(const float4*)(S_yf + off);
        float4 q = *(const float4*)(S_yb + off);
        stage4(As + m*128, (m&1)<<4, c, a.x+q.x, a.y+q.y, a.z+q.z, a.w+q.w);
    }
    __syncthreads();

    float acc[2][3][4] = {};
    gemm_ldgB<8,128>(As, 128, WoP, wm, wn, gid, tq, acc);

    #pragma unroll
    for (int mt = 0; mt < 2; mt++) {
        int r = wm*32 + mt*16 + gid;
        #pragma unroll
        for (int nt = 0; nt < 3; nt++) {
            int c = wn*24 + nt*8 + tq*2;
            x1s[r*100 + c]     = acc[mt][nt][0];
            x1s[r*100 + c + 1] = acc[mt][nt][1];
            x1s[(r+8)*100 + c]     = acc[mt][nt][2];
            x1s[(r+8)*100 + c + 1] = acc[mt][nt][3];
        }
    }
    __syncthreads();

    // ---- residual + LN + loan2 -> tts ----
    {
        // hoisted swizzled column indices for this lane
        int jp0 = kperm16(lane*3 + 0);
        int jp1 = kperm16(lane*3 + 1);
        int jp2 = kperm16(lane*3 + 2);
        for (int r = warp; r < 64; r += 8) {
            int gm = m_base + r;
            size_t base = (size_t)Goff[gm];
            size_t xb = base*96;
            float v0 = x1s[r*100 + lane*3 + 0] + x[xb + lane*3 + 0];
            float v1 = x1s[r*100 + lane*3 + 1] + x[xb + lane*3 + 1];
            float v2 = x1s[r*100 + lane*3 + 2] + x[xb + lane*3 + 2];
            x1s[r*100 + lane*3 + 0] = v0;
            x1s[r*100 + lane*3 + 1] = v1;
            x1s[r*100 + lane*3 + 2] = v2;
            float s1 = v0+v1+v2, s2 = v0*v0+v1*v1+v2*v2;
            #pragma unroll
            for (int o = 16; o > 0; o >>= 1) {
                s1 += __shfl_xor_sync(0xffffffffu, s1, o);
                s2 += __shfl_xor_sync(0xffffffffu, s2, o);
            }
            float mu  = s1 * (1.0f/96.0f);
            float var = s2 * (1.0f/96.0f) - mu*mu;
            float rs  = rsqrtf(var + 1e-5f);
            size_t sbase = base*8;
            float xs[8];
            #pragma unroll
            for (int k = 0; k < 8; k++) xs[k] = xstat[sbase + k];
            int swr = (r & 1) << 4;
            float av0 = lb2[lane*3+0], av1 = lb2[lane*3+1], av2 = lb2[lane*3+2];
            #pragma unroll
            for (int k = 0; k < 8; k++) {
                av0 = fmaf(xs[k], ls2[k*96 + lane*3 + 0], av0);
                av1 = fmaf(xs[k], ls2[k*96 + lane*3 + 1], av1);
                av2 = fmaf(xs[k], ls2[k*96 + lane*3 + 2], av2);
            }
            tts[r*96 + (jp0 ^ swr)] = f2tf32((v0 - mu)*rs + tanhf(av0));
            tts[r*96 + (jp1 ^ swr)] = f2tf32((v1 - mu)*rs + tanhf(av1));
            tts[r*96 + (jp2 ^ swr)] = f2tf32((v2 - mu)*rs + tanhf(av2));
        }
    }
    __syncthreads();

    float acc1[2][3][4] = {};
    gemm_ldgB<6,96>(tts, 96, W1P, wm, wn, gid, tq, acc1);
    __syncthreads();

    #pragma unroll
    for (int mt = 0; mt < 2; mt++) {
        int r = wm*32 + mt*16 + gid;
        int swr = (r & 1) << 4;
        #pragma unroll
        for (int nt = 0; nt < 3; nt++) {
            int c = wn*24 + nt*8 + tq*2;
            float bb0 = b1[c], bb1 = b1[c+1];
            hs[r*96 + (kperm16(c)   ^ swr)] = f2tf32(geluf(acc1[mt][nt][0] + bb0));
            hs[r*96 + (kperm16(c+1) ^ swr)] = f2tf32(geluf(acc1[mt][nt][1] + bb1));
            hs[(r+8)*96 + (kperm16(c)   ^ swr)] = f2tf32(geluf(acc1[mt][nt][2] + bb0));
            hs[(r+8)*96 + (kperm16(c+1) ^ swr)] = f2tf32(geluf(acc1[mt][nt][3] + bb1));
        }
    }
    __syncthreads();

    float acc2[2][3][4] = {};
    gemm_ldgB<6,96>(hs, 96, W2P, wm, wn, gid, tq, acc2);

    #pragma unroll
    for (int mt = 0; mt < 2; mt++) {
        int r = wm*32 + mt*16 + gid;
        int gm0 = m_base + r, gm8 = gm0 + 8;
        #pragma unroll
        for (int nt = 0; nt < 3; nt++) {
            int c = wn*24 + nt*8 + tq*2;
            float bb0 = b2[c], bb1 = b2[c+1];
            *(float2*)(out + (size_t)gm0*96 + c) = make_float2(
                acc2[mt][nt][0] + bb0 + x1s[r*100 + c],
                acc2[mt][nt][1] + bb1 + x1s[r*100 + c + 1]);
            *(float2*)(out + (size_t)gm8*96 + c) = make_float2(
                acc2[mt][nt][2] + bb0 + x1s[(r+8)*100 + c],
                acc2[mt][nt][3] + bb1 + x1s[(r+8)*100 + c + 1]);
        }
    }
}

// ================= launcher =================
extern "C" void kernel_launch(void* const* d_in, const int* in_sizes, int n_in,
                              void* d_out, int out_size)
{
    const float* x       = (const float*)d_in[0];
    const float* xstat   = (const float*)d_in[1];
    const float* xhres   = (const float*)d_in[2];
    const int*   curves  = (const int*)  d_in[3];
    const float* embed_w = (const float*)d_in[4];
    const float* embed_b = (const float*)d_in[5];
    const float* loan1_w = (const float*)d_in[6];
    const float* loan1_b = (const float*)d_in[7];
    const float* loan2_w = (const float*)d_in[8];
    const float* loan2_b = (const float*)d_in[9];
    const float* in_proj = (const float*)d_in[10];
    const float* cw_f  = (const float*)d_in[11];
    const float* cb_f  = (const float*)d_in[12];
    const float* dtb_f = (const float*)d_in[13];
    const float* al_f  = (const float*)d_in[14];
    const float* Dp_f  = (const float*)d_in[15];
    const float* nw_f  = (const float*)d_in[16];
    const float* cw_b  = (const float*)d_in[17];
    const float* cb_b  = (const float*)d_in[18];
    const float* dtb_b = (const float*)d_in[19];
    const float* al_b  = (const float*)d_in[20];
    const float* Dp_b  = (const float*)d_in[21];
    const float* nw_b  = (const float*)d_in[22];
    const float* Wo    = (const float*)d_in[23];
    const float* W1    = (const float*)d_in[24];
    const float* b1    = (const float*)d_in[25];
    const float* W2    = (const float*)d_in[26];
    const float* b2    = (const float*)d_in[27];
    float* out = (float*)d_out;

    const int smem012 = (64*268 + 64*128 + 960) * 4;          // 105216
    const int smem34  = (64*128 + 64*100 + 768 + 96) * 4;     // 61824

    cudaFuncSetAttribute(k012_fused, cudaFuncAttributeMaxDynamicSharedMemorySize, smem012);
    cudaFuncSetAttribute(k34_fused,  cudaFuncAttributeMaxDynamicSharedMemorySize, smem34);

    kprep<<<NTOK/256, 256>>>(in_proj, Wo, W1, W2, curves);

    k012_fused<<<4096, 256, smem012>>>(x, xstat, xhres,
                                       embed_w, embed_b, loan1_w, loan1_b,
                                       cw_f, cb_f, dtb_f, al_f, Dp_f, nw_f,
                                       cw_b, cb_b, dtb_b, al_b, Dp_b, nw_b);

    k34_fused<<<NTOK/64, 256, smem34>>>(x, xstat, loan2_w, loan2_b, b1, b2, out);
}

// round 11
// speedup vs baseline: 1.3491x; 1.0192x over previous
#include <cuda_runtime.h>
#include <math.h>

#define BB 2
#define TT 6
#define PP 20480
#define NTOK (BB*TT*PP)      /* 245760 */
#define DPROJ 266

// ---------------- scratch ----------------
__device__ float S_yf[(size_t)NTOK*128];
__device__ float S_yb[(size_t)NTOK*128];
__device__ int   Goff[NTOK];
// pre-permuted tf32 weights (B operands, n-major, kperm16'd)
__device__ unsigned Wp1[320*128];
__device__ unsigned WoP[96*128];
__device__ unsigned W1P[96*96];
__device__ unsigned W2P[96*96];

__device__ __forceinline__ float geluf(float v) {
    return 0.5f * v * (1.0f + erff(v * 0.70710678118654752f));
}
__device__ __forceinline__ unsigned f2tf32(float f) {
    unsigned r;
    asm("cvt.rna.tf32.f32 %0, %1;" : "=r"(r) : "f"(f));
    return r;
}
__device__ __forceinline__ int kperm16(int k) {
    int g = k & ~15, j = k & 15;
    return g + ((j & 3) << 2) + (j >> 2);
}
__device__ __forceinline__ void mma_tf32(float* c, const unsigned* a, const unsigned* b) {
    asm volatile(
        "mma.sync.aligned.m16n8k8.row.col.f32.tf32.tf32.f32 "
        "{%0,%1,%2,%3}, {%4,%5,%6,%7}, {%8,%9}, {%0,%1,%2,%3};"
        : "+f"(c[0]), "+f"(c[1]), "+f"(c[2]), "+f"(c[3])
        : "r"(a[0]), "r"(a[1]), "r"(a[2]), "r"(a[3]), "r"(b[0]), "r"(b[1]));
}
__device__ __forceinline__ void stage4(unsigned* row, int sw, int c, float x, float y, float z, float w) {
    int g = (c >> 2) << 4, r = c & 3;
    row[(g + r     ) ^ sw] = f2tf32(x);
    row[(g + r + 4 ) ^ sw] = f2tf32(y);
    row[(g + r + 8 ) ^ sw] = f2tf32(z);
    row[(g + r + 12) ^ sw] = f2tf32(w);
}

// ================= prep: weights + gather offsets =================
__global__ void kprep(const float* __restrict__ inproj, const float* __restrict__ Wo,
                      const float* __restrict__ W1, const float* __restrict__ W2,
                      const int* __restrict__ curves)
{
    int i = blockIdx.x * 256 + threadIdx.x;
    if (i < 320*128) {
        int n = i >> 7, k = i & 127;
        float v = (n < DPROJ) ? inproj[(size_t)k*DPROJ + n] : 0.0f;
        Wp1[n*128 + kperm16(k)] = f2tf32(v);
    }
    if (i < 96*128) {
        int n = i >> 7, k = i & 127;
        WoP[n*128 + kperm16(k)] = f2tf32(Wo[(size_t)k*96 + n]);
    }
    if (i < 96*96) {
        int n = i / 96, k = i - n*96;
        W1P[n*96 + kperm16(k)] = f2tf32(W1[(size_t)k*96 + n]);
        W2P[n*96 + kperm16(k)] = f2tf32(W2[(size_t)k*96 + n]);
    }
    if (i < NTOK) {
        int b  = i / (TT*PP);
        int tp = i - b*TT*PP;
        int t  = tp / PP;
        int p  = tp - t*PP;
        Goff[i] = (b*TT + t)*PP + curves[b*PP + p];
    }
}

// ================= K012: prologue + in_proj GEMM + mamba (R5 + N=288 trim) =====
// CTA = (b, tg, qgrp): 60 tokens (3 t x 20 p), GEMM in smem, 2 fwd + 2 bwd scans.
// 256 threads, 2 CTAs/SM. Grid = 4096.
__global__ void __launch_bounds__(256, 2) k012_fused(
    const float* __restrict__ x,
    const float* __restrict__ xstat,
    const float* __restrict__ xhres,
    const float* __restrict__ embed_w,
    const float* __restrict__ embed_b,
    const float* __restrict__ loan1_w,
    const float* __restrict__ loan1_b,
    const float* __restrict__ cw_f, const float* __restrict__ cb_f,
    const float* __restrict__ dtb_f, const float* __restrict__ al_f,
    const float* __restrict__ Dp_f, const float* __restrict__ nw_f,
    const float* __restrict__ cw_b, const float* __restrict__ cb_b,
    const float* __restrict__ dtb_b, const float* __restrict__ al_b,
    const float* __restrict__ Dp_b, const float* __restrict__ nw_b)
{
    extern __shared__ float smx[];
    float*    u_s = smx;                     // [64][268] fp32
    float*    ovl = smx + 64*268;            // overlay: As (GEMM) then xc0/xc1
    unsigned* As  = (unsigned*)ovl;          // [64][128] swizzled tf32
    float*    dtA = smx + 64*268 + 64*128;   // dt[2][240] dA[2][240]
    __shared__ float Aneg[2][8];

    const int blk  = blockIdx.x;
    const int b    = blk >> 11;
    const int tg   = (blk >> 10) & 1;
    const int qgrp = blk & 1023;
    const int tid  = threadIdx.x;
    const int warp = tid >> 5, lane = tid & 31;

    // ---- prologue: warp-per-token, 8 passes over 64 rows (60 real) ----
    for (int pass = 0; pass < 8; pass++) {
        const int m = pass*8 + warp;
        if (m < 60) {
            const int t_loc = m / 20;
            const int p_loc = m - t_loc*20;
            const int gi = (b*TT + tg*3 + t_loc)*PP + qgrp*20 + p_loc;
            const size_t base = (size_t)Goff[gi];

            float hval = (lane < 28) ? xhres[base*28 + lane] : 0.0f;
            float sval = (lane < 8)  ? xstat[base*8 + lane]  : 0.0f;

            const int j0 = (lane >= 24) ? (lane - 24) * 4 : 0;
            float a0 = embed_b[j0], a1 = embed_b[j0+1], a2 = embed_b[j0+2], a3 = embed_b[j0+3];
            #pragma unroll
            for (int k = 0; k < 28; k++) {
                float hk = __shfl_sync(0xffffffffu, hval, k);
                a0 = fmaf(hk, embed_w[k*32 + j0    ], a0);
                a1 = fmaf(hk, embed_w[k*32 + j0 + 1], a1);
                a2 = fmaf(hk, embed_w[k*32 + j0 + 2], a2);
                a3 = fmaf(hk, embed_w[k*32 + j0 + 3], a3);
            }
            float v0, v1, v2, v3;
            if (lane < 24) {
                float4 xv = *(const float4*)(x + base*96 + lane*4);
                v0 = xv.x; v1 = xv.y; v2 = xv.z; v3 = xv.w;
            } else {
                v0 = tanhf(a0); v1 = tanhf(a1); v2 = tanhf(a2); v3 = tanhf(a3);
            }
            float s1 = v0+v1+v2+v3;
            float s2 = v0*v0+v1*v1+v2*v2+v3*v3;
            #pragma unroll
            for (int o = 16; o > 0; o >>= 1) {
                s1 += __shfl_xor_sync(0xffffffffu, s1, o);
                s2 += __shfl_xor_sync(0xffffffffu, s2, o);
            }
            float mu  = s1 * (1.0f/128.0f);
            float var = s2 * (1.0f/128.0f) - mu*mu;
            float rs  = rsqrtf(var + 1e-5f);
            float sv[8];
            #pragma unroll
            for (int k = 0; k < 8; k++) sv[k] = __shfl_sync(0xffffffffu, sval, k);
            const int c = lane*4;
            float o0 = loan1_b[c], o1 = loan1_b[c+1], o2 = loan1_b[c+2], o3 = loan1_b[c+3];
            #pragma unroll
            for (int k = 0; k < 8; k++) {
                o0 = fmaf(sv[k], loan1_w[k*128 + c    ], o0);
                o1 = fmaf(sv[k], loan1_w[k*128 + c + 1], o1);
                o2 = fmaf(sv[k], loan1_w[k*128 + c + 2], o2);
                o3 = fmaf(sv[k], loan1_w[k*128 + c + 3], o3);
            }
            o0 = (v0 - mu)*rs + tanhf(o0);
            o1 = (v1 - mu)*rs + tanhf(o1);
            o2 = (v2 - mu)*rs + tanhf(o2);
            o3 = (v3 - mu)*rs + tanhf(o3);
            stage4(As + m*128, (m&1)<<4, lane, o0, o1, o2, o3);
        } else {
            stage4(As + m*128, (m&1)<<4, lane, 0.f, 0.f, 0.f, 0.f);
        }
    }
    __syncthreads();

    // ---- GEMM: u = xn @ Wp1, M=64, K=128, into u_s ----
    // chunk0: N=160 (cols 0..159, nt=5); chunk1: N=128 (cols 160..287, nt=4).
    // Cols 288..319 of Wp1 are zero-padding -> skipped entirely (identical output).
    {
        const int gid = lane >> 2, tq = lane & 3;
        const int wm = warp & 1, wn = warp >> 1;

        // chunk0: cols 0..159
        {
            float acc[2][5][4] = {};
            #pragma unroll
            for (int it = 0; it < 8; it++) {
                const int cb = it*16 + tq*4;
                uint4 a0v[2], a8v[2], bv[5];
                #pragma unroll
                for (int mt = 0; mt < 2; mt++) {
                    int r0 = wm*32 + mt*16 + gid;
                    int sw = (r0 & 1) << 4;
                    a0v[mt] = *(const uint4*)(As + r0*128 + (cb ^ sw));
                    a8v[mt] = *(const uint4*)(As + (r0+8)*128 + (cb ^ sw));
                }
                #pragma unroll
                for (int nt = 0; nt < 5; nt++) {
                    int nr = wn*40 + nt*8 + gid;
                    bv[nt] = *(const uint4*)(Wp1 + nr*128 + cb);
                }
                #pragma unroll
                for (int mt = 0; mt < 2; mt++) {
                    #pragma unroll
                    for (int nt = 0; nt < 5; nt++) {
                        unsigned aa1[4] = {a0v[mt].x, a8v[mt].x, a0v[mt].y, a8v[mt].y};
                        unsigned bb1[2] = {bv[nt].x, bv[nt].y};
                        mma_tf32(acc[mt][nt], aa1, bb1);
                        unsigned aa2[4] = {a0v[mt].z, a8v[mt].z, a0v[mt].w, a8v[mt].w};
                        unsigned bb2[2] = {bv[nt].z, bv[nt].w};
                        mma_tf32(acc[mt][nt], aa2, bb2);
                    }
                }
            }
            #pragma unroll
            for (int mt = 0; mt < 2; mt++) {
                int row = wm*32 + mt*16 + gid;
                #pragma unroll
                for (int nt = 0; nt < 5; nt++) {
                    int col = wn*40 + nt*8 + tq*2;   // <= 158, always < DPROJ
                    *(float2*)(u_s + row*268 + col) =
                        make_float2(acc[mt][nt][0], acc[mt][nt][1]);
                    *(float2*)(u_s + (row+8)*268 + col) =
                        make_float2(acc[mt][nt][2], acc[mt][nt][3]);
                }
            }
        }
        // chunk1: cols 160..287 (only 160..265 stored)
        {
            float acc[2][4][4] = {};
            #pragma unroll
            for (int it = 0; it < 8; it++) {
                const int cb = it*16 + tq*4;
                uint4 a0v[2], a8v[2], bv[4];
                #pragma unroll
                for (int mt = 0; mt < 2; mt++) {
                    int r0 = wm*32 + mt*16 + gid;
                    int sw = (r0 & 1) << 4;
                    a0v[mt] = *(const uint4*)(As + r0*128 + (cb ^ sw));
                    a8v[mt] = *(const uint4*)(As + (r0+8)*128 + (cb ^ sw));
                }
                #pragma unroll
                for (int nt = 0; nt < 4; nt++) {
                    int nr = 160 + wn*32 + nt*8 + gid;
                    bv[nt] = *(const uint4*)(Wp1 + nr*128 + cb);
                }
                #pragma unroll
                for (int mt = 0; mt < 2; mt++) {
                    #pragma unroll
                    for (int nt = 0; nt < 4; nt++) {
                        unsigned aa1[4] = {a0v[mt].x, a8v[mt].x, a0v[mt].y, a8v[mt].y};
                        unsigned bb1[2] = {bv[nt].x, bv[nt].y};
                        mma_tf32(acc[mt][nt], aa1, bb1);
                        unsigned aa2[4] = {a0v[mt].z, a8v[mt].z, a0v[mt].w, a8v[mt].w};
                        unsigned bb2[2] = {bv[nt].z, bv[nt].w};
                        mma_tf32(acc[mt][nt], aa2, bb2);
                    }
                }
            }
            #pragma unroll
            for (int mt = 0; mt < 2; mt++) {
                int row = wm*32 + mt*16 + gid;
                #pragma unroll
                for (int nt = 0; nt < 4; nt++) {
                    int col = 160 + wn*32 + nt*8 + tq*2;
                    if (col < DPROJ) {
                        *(float2*)(u_s + row*268 + col) =
                            make_float2(acc[mt][nt][0], acc[mt][nt][1]);
                        *(float2*)(u_s + (row+8)*268 + col) =
                            make_float2(acc[mt][nt][2], acc[mt][nt][3]);
                    }
                }
            }
        }
    }
    if (tid < 16) Aneg[tid>>3][tid&7] = -expf((tid < 8 ? al_f : al_b)[tid & 7]);
    __syncthreads();   // u_s complete; As region free -> xc overlay

    // ---- mamba: 2 rounds (fwd, bwd); group g = seq (qg = qgrp*2+g) ----
    const int g  = tid >> 7;
    const int lt = tid & 127;
    float* xcg = ovl + g*3960;           // [30][132]
    float* dts = dtA + g*240;
    float* dAs = dtA + 480 + g*240;
    const int qg_src = qgrp*2 + g;

    #pragma unroll
    for (int r = 0; r < 2; r++) {
        const float* conv_w = r ? cw_b  : cw_f;
        const float* conv_b = r ? cb_b  : cb_f;
        const float* dtbp   = r ? dtb_b : dtb_f;
        const float* Dpp    = r ? Dp_b  : Dp_f;

        for (int i = lt; i < 240; i += 128) {
            int l = i >> 3, h = i & 7;
            int l10 = l / 10, lr = l - l10*10;
            int lu_r = r ? (9 - lr) : lr;
            int mu_ = l10*20 + g*10 + lu_r;
            float raw = u_s[mu_*268 + 258 + h] + dtbp[h];
            float dt = (raw > 20.f) ? raw : log1pf(expf(raw));
            dts[l*8 + h] = dt;
            dAs[l*8 + h] = expf(dt * Aneg[r][h]);
        }
        for (int c = lt; c < 130; c += 128) {
            float w0 = conv_w[c*3+0], w1 = conv_w[c*3+1], w2 = conv_w[c*3+2];
            float bias = conv_b[c];
            float p2 = 0.f, p1 = 0.f;
            #pragma unroll
            for (int l = 0; l < 30; l++) {
                int l10 = l / 10, lr = l - l10*10;
                int mu_ = l10*20 + g*10 + (r ? (9 - lr) : lr);
                float v = u_s[mu_*268 + 128 + c];
                float a = fmaf(p2, w0, fmaf(p1, w1, fmaf(v, w2, bias)));
                xcg[l*132 + c] = a / (1.f + expf(-a));
                p2 = p1; p1 = v;
            }
        }
        __syncthreads();

        {
            const int c = lt, h = c >> 4;
            const float Dh = Dpp[h];
            float hs = 0.f;
            #pragma unroll
            for (int l = 0; l < 30; l++) {
                int l10 = l / 10, lr = l - l10*10;
                int mu_ = l10*20 + g*10 + (r ? (9 - lr) : lr);
                float xv = xcg[l*132 + c];
                float Bv = xcg[l*132 + 128];
                float Cv = xcg[l*132 + 129];
                hs = fmaf(hs, dAs[l*8+h], dts[l*8+h]*xv*Bv);
                float y = fmaf(hs, Cv, xv*Dh);
                float z = u_s[mu_*268 + c];
                y *= z / (1.f + expf(-z));
                xcg[l*132 + c] = y;
            }
        }
        __syncthreads();

        {
            const int w4 = warp & 3;
            const float* nww = r ? nw_b : nw_f;
            float* ybuf = r ? S_yb : S_yf;
            const int qgu = r ? (2047 - qg_src) : qg_src;
            const int abase = (tg*1024 + (qgu>>1))*6 + (qgu&1);
            for (int l = w4; l < 30; l += 4) {
                float4 v = *(float4*)(xcg + l*132 + lane*4);
                float ss = v.x*v.x + v.y*v.y + v.z*v.z + v.w*v.w;
                #pragma unroll
                for (int o = 16; o > 0; o >>= 1) ss += __shfl_xor_sync(0xffffffffu, ss, o);
                float scale = rsqrtf(ss*(1.f/128.f) + 1e-5f) * 0.5f;
                int l3 = l / 3;
                int f = l3*12288 + abase + (l - l3*3)*2;
                int t_out = f / PP;
                int p_out = f - t_out*PP;
                if (r) p_out = PP-1 - p_out;
                float4 w = *(const float4*)(nww + lane*4);
                float4 o;
                o.x = v.x*scale*w.x; o.y = v.y*scale*w.y;
                o.z = v.z*scale*w.z; o.w = v.w*scale*w.w;
                *(float4*)(ybuf + ((size_t)(b*TT + t_out)*PP + p_out)*128 + lane*4) = o;
            }
        }
        __syncthreads();
    }
}

// ===== GEMM helper: M64xN96, A in smem, B via LDG =====
template<int KIT, int KSTRIDE>
__device__ __forceinline__ void gemm_ldgB(const unsigned* __restrict__ Ab, int SA,
                                          const unsigned* __restrict__ Wg,
                                          int wm, int wn, int gid, int tq,
                                          float (&acc)[2][3][4])
{
    #pragma unroll
    for (int it = 0; it < KIT; it++) {
        const int cb = it*16 + tq*4;
        uint4 a0v[2], a8v[2], bv[3];
        #pragma unroll
        for (int mt = 0; mt < 2; mt++) {
            int r0 = wm*32 + mt*16 + gid;
            int sw = (r0 & 1) << 4;
            a0v[mt] = *(const uint4*)(Ab + r0*SA + (cb ^ sw));
            a8v[mt] = *(const uint4*)(Ab + (r0+8)*SA + (cb ^ sw));
        }
        #pragma unroll
        for (int nt = 0; nt < 3; nt++) {
            int nr = wn*24 + nt*8 + gid;
            bv[nt] = *(const uint4*)(Wg + nr*KSTRIDE + cb);
        }
        #pragma unroll
        for (int mt = 0; mt < 2; mt++) {
            #pragma unroll
            for (int nt = 0; nt < 3; nt++) {
                unsigned aa1[4] = {a0v[mt].x, a8v[mt].x, a0v[mt].y, a8v[mt].y};
                unsigned bb1[2] = {bv[nt].x, bv[nt].y};
                mma_tf32(acc[mt][nt], aa1, bb1);
                unsigned aa2[4] = {a0v[mt].z, a8v[mt].z, a0v[mt].w, a8v[mt].w};
                unsigned bb2[2] = {bv[nt].z, bv[nt].w};
                mma_tf32(acc[mt][nt], aa2, bb2);
            }
        }
    }
}

// ================= K34: out_proj + residual + LN + loan2 + MLP, fused (R5) ==========
__global__ void __launch_bounds__(256, 3) k34_fused(
    const float* __restrict__ x,
    const float* __restrict__ xstat,
    const float* __restrict__ loan2_w,
    const float* __restrict__ loan2_b,
    const float* __restrict__ b1,
    const float* __restrict__ b2,
    float* __restrict__ out)
{
    extern __shared__ unsigned smf[];
    unsigned* As  = smf;                     // [64][128]; tts/hs overlay
    float*    x1s = (float*)(smf + 64*128);  // [64][100]
    unsigned* tts = As;
    unsigned* hs  = As;

    const int tid = threadIdx.x;
    const int m_base = blockIdx.x * 64;
    const int warp = tid >> 5, lane = tid & 31;
    const int gid = lane >> 2, tq = lane & 3;
    const int wm = warp & 1, wn = warp >> 1;

    for (int i = tid; i < 64*32; i += 256) {
        int m = i >> 5, c = i & 31;
        size_t off = (size_t)(m_base+m)*128 + c*4;
        float4 a = *(const float4*)(S_yf + off);
        float4 q = *(const float4*)(S_yb + off);
        stage4(As + m*128, (m&1)<<4, c, a.x+q.x, a.y+q.y, a.z+q.z, a.w+q.w);
    }
    __syncthreads();

    float acc[2][3][4] = {};
    gemm_ldgB<8,128>(As, 128, WoP, wm, wn, gid, tq, acc);

    #pragma unroll
    for (int mt = 0; mt < 2; mt++) {
        int r = wm*32 + mt*16 + gid;
        #pragma unroll
        for (int nt = 0; nt < 3; nt++) {
            int c = wn*24 + nt*8 + tq*2;
            x1s[r*100 + c]     = acc[mt][nt][0];
            x1s[r*100 + c + 1] = acc[mt][nt][1];
            x1s[(r+8)*100 + c]     = acc[mt][nt][2];
            x1s[(r+8)*100 + c + 1] = acc[mt][nt][3];
        }
    }
    __syncthreads();

    for (int r = warp; r < 64; r += 8) {
        int gm = m_base + r;
        size_t base = (size_t)Goff[gm];
        size_t xb = base*96;
        float v0 = x1s[r*100 + lane*3 + 0] + x[xb + lane*3 + 0];
        float v1 = x1s[r*100 + lane*3 + 1] + x[xb + lane*3 + 1];
        float v2 = x1s[r*100 + lane*3 + 2] + x[xb + lane*3 + 2];
        x1s[r*100 + lane*3 + 0] = v0;
        x1s[r*100 + lane*3 + 1] = v1;
        x1s[r*100 + lane*3 + 2] = v2;
        float s1 = v0+v1+v2, s2 = v0*v0+v1*v1+v2*v2;
        #pragma unroll
        for (int o = 16; o > 0; o >>= 1) {
            s1 += __shfl_xor_sync(0xffffffffu, s1, o);
            s2 += __shfl_xor_sync(0xffffffffu, s2, o);
        }
        float mu  = s1 * (1.0f/96.0f);
        float var = s2 * (1.0f/96.0f) - mu*mu;
        float rs  = rsqrtf(var + 1e-5f);
        size_t sbase = base*8;
        float xs[8];
        #pragma unroll
        for (int k = 0; k < 8; k++) xs[k] = xstat[sbase + k];
        int swr = (r & 1) << 4;
        #pragma unroll
        for (int i2 = 0; i2 < 3; i2++) {
            int jj = lane*3 + i2;
            float a = loan2_b[jj];
            #pragma unroll
            for (int k = 0; k < 8; k++) a = fmaf(xs[k], loan2_w[k*96 + jj], a);
            float vv = (i2 == 0) ? v0 : ((i2 == 1) ? v1 : v2);
            tts[r*96 + (kperm16(jj) ^ swr)] = f2tf32((vv - mu)*rs + tanhf(a));
        }
    }
    __syncthreads();

    float acc1[2][3][4] = {};
    gemm_ldgB<6,96>(tts, 96, W1P, wm, wn, gid, tq, acc1);
    __syncthreads();

    #pragma unroll
    for (int mt = 0; mt < 2; mt++) {
        int r = wm*32 + mt*16 + gid;
        int swr = (r & 1) << 4;
        #pragma unroll
        for (int nt = 0; nt < 3; nt++) {
            int c = wn*24 + nt*8 + tq*2;
            float bb0 = b1[c], bb1 = b1[c+1];
            hs[r*96 + (kperm16(c)   ^ swr)] = f2tf32(geluf(acc1[mt][nt][0] + bb0));
            hs[r*96 + (kperm16(c+1) ^ swr)] = f2tf32(geluf(acc1[mt][nt][1] + bb1));
            hs[(r+8)*96 + (kperm16(c)   ^ swr)] = f2tf32(geluf(acc1[mt][nt][2] + bb0));
            hs[(r+8)*96 + (kperm16(c+1) ^ swr)] = f2tf32(geluf(acc1[mt][nt][3] + bb1));
        }
    }
    __syncthreads();

    float acc2[2][3][4] = {};
    gemm_ldgB<6,96>(hs, 96, W2P, wm, wn, gid, tq, acc2);

    #pragma unroll
    for (int mt = 0; mt < 2; mt++) {
        int r = wm*32 + mt*16 + gid;
        int gm0 = m_base + r, gm8 = gm0 + 8;
        #pragma unroll
        for (int nt = 0; nt < 3; nt++) {
            int c = wn*24 + nt*8 + tq*2;
            float bb0 = b2[c], bb1 = b2[c+1];
            *(float2*)(out + (size_t)gm0*96 + c) = make_float2(
                acc2[mt][nt][0] + bb0 + x1s[r*100 + c],
                acc2[mt][nt][1] + bb1 + x1s[r*100 + c + 1]);
            *(float2*)(out + (size_t)gm8*96 + c) = make_float2(
                acc2[mt][nt][2] + bb0 + x1s[(r+8)*100 + c],
                acc2[mt][nt][3] + bb1 + x1s[(r+8)*100 + c + 1]);
        }
    }
}

// ================= launcher =================
extern "C" void kernel_launch(void* const* d_in, const int* in_sizes, int n_in,
                              void* d_out, int out_size)
{
    const float* x       = (const float*)d_in[0];
    const float* xstat   = (const float*)d_in[1];
    const float* xhres   = (const float*)d_in[2];
    const int*   curves  = (const int*)  d_in[3];
    const float* embed_w = (const float*)d_in[4];
    const float* embed_b = (const float*)d_in[5];
    const float* loan1_w = (const float*)d_in[6];
    const float* loan1_b = (const float*)d_in[7];
    const float* loan2_w = (const float*)d_in[8];
    const float* loan2_b = (const float*)d_in[9];
    const float* in_proj = (const float*)d_in[10];
    const float* cw_f  = (const float*)d_in[11];
    const float* cb_f  = (const float*)d_in[12];
    const float* dtb_f = (const float*)d_in[13];
    const float* al_f  = (const float*)d_in[14];
    const float* Dp_f  = (const float*)d_in[15];
    const float* nw_f  = (const float*)d_in[16];
    const float* cw_b  = (const float*)d_in[17];
    const float* cb_b  = (const float*)d_in[18];
    const float* dtb_b = (const float*)d_in[19];
    const float* al_b  = (const float*)d_in[20];
    const float* Dp_b  = (const float*)d_in[21];
    const float* nw_b  = (const float*)d_in[22];
    const float* Wo    = (const float*)d_in[23];
    const float* W1    = (const float*)d_in[24];
    const float* b1    = (const float*)d_in[25];
    const float* W2    = (const float*)d_in[26];
    const float* b2    = (const float*)d_in[27];
    float* out = (float*)d_out;

    const int smem012 = (64*268 + 64*128 + 960) * 4;   // 105216
    const int smem34  = (64*128 + 64*100) * 4;         // 58368

    cudaFuncSetAttribute(k012_fused, cudaFuncAttributeMaxDynamicSharedMemorySize, smem012);
    cudaFuncSetAttribute(k34_fused,  cudaFuncAttributeMaxDynamicSharedMemorySize, smem34);

    kprep<<<NTOK/256, 256>>>(in_proj, Wo, W1, W2, curves);

    k012_fused<<<4096, 256, smem012>>>(x, xstat, xhres,
                                       embed_w, embed_b, loan1_w, loan1_b,
                                       cw_f, cb_f, dtb_f, al_f, Dp_f, nw_f,
                                       cw_b, cb_b, dtb_b, al_b, Dp_b, nw_b);

    k34_fused<<<NTOK/64, 256, smem34>>>(x, xstat, loan2_w, loan2_b, b1, b2, out);
}

// round 12
// speedup vs baseline: 1.4039x; 1.0406x over previous
#include <cuda_runtime.h>
#include <math.h>

#define BB 2
#define TT 6
#define PP 20480
#define NTOK (BB*TT*PP)      /* 245760 */
#define DPROJ 266

// ---------------- scratch ----------------
__device__ float S_yf[(size_t)NTOK*128];
__device__ float S_yb[(size_t)NTOK*128];
__device__ int   Goff[NTOK];
// pre-permuted tf32 weights (B operands, n-major, kperm16'd)
__device__ unsigned Wp1[320*128];
__device__ unsigned WoP[96*128];
__device__ unsigned W1P[96*96];
__device__ unsigned W2P[96*96];

__device__ __forceinline__ float geluf(float v) {
    return 0.5f * v * (1.0f + erff(v * 0.70710678118654752f));
}
__device__ __forceinline__ unsigned f2tf32(float f) {
    unsigned r;
    asm("cvt.rna.tf32.f32 %0, %1;" : "=r"(r) : "f"(f));
    return r;
}
__device__ __forceinline__ int kperm16(int k) {
    int g = k & ~15, j = k & 15;
    return g + ((j & 3) << 2) + (j >> 2);
}
__device__ __forceinline__ void mma_tf32(float* c, const unsigned* a, const unsigned* b) {
    asm volatile(
        "mma.sync.aligned.m16n8k8.row.col.f32.tf32.tf32.f32 "
        "{%0,%1,%2,%3}, {%4,%5,%6,%7}, {%8,%9}, {%0,%1,%2,%3};"
        : "+f"(c[0]), "+f"(c[1]), "+f"(c[2]), "+f"(c[3])
        : "r"(a[0]), "r"(a[1]), "r"(a[2]), "r"(a[3]), "r"(b[0]), "r"(b[1]));
}
__device__ __forceinline__ void stage4(unsigned* row, int sw, int c, float x, float y, float z, float w) {
    int g = (c >> 2) << 4, r = c & 3;
    row[(g + r     ) ^ sw] = f2tf32(x);
    row[(g + r + 4 ) ^ sw] = f2tf32(y);
    row[(g + r + 8 ) ^ sw] = f2tf32(z);
    row[(g + r + 12) ^ sw] = f2tf32(w);
}

// ================= prep: weights + gather offsets =================
__global__ void kprep(const float* __restrict__ inproj, const float* __restrict__ Wo,
                      const float* __restrict__ W1, const float* __restrict__ W2,
                      const int* __restrict__ curves)
{
    int i = blockIdx.x * 256 + threadIdx.x;
    if (i < 320*128) {
        int n = i >> 7, k = i & 127;
        float v = (n < DPROJ) ? inproj[(size_t)k*DPROJ + n] : 0.0f;
        Wp1[n*128 + kperm16(k)] = f2tf32(v);
    }
    if (i < 96*128) {
        int n = i >> 7, k = i & 127;
        WoP[n*128 + kperm16(k)] = f2tf32(Wo[(size_t)k*96 + n]);
    }
    if (i < 96*96) {
        int n = i / 96, k = i - n*96;
        W1P[n*96 + kperm16(k)] = f2tf32(W1[(size_t)k*96 + n]);
        W2P[n*96 + kperm16(k)] = f2tf32(W2[(size_t)k*96 + n]);
    }
    if (i < NTOK) {
        int b  = i / (TT*PP);
        int tp = i - b*TT*PP;
        int t  = tp / PP;
        int p  = tp - t*PP;
        Goff[i] = (b*TT + t)*PP + curves[b*PP + p];
    }
}

// ================= K012: prologue + in_proj GEMM + mamba =================
// R11 + fast-math transcendentals + fused B/C conv.
// CTA = (b, tg, qgrp): 60 tokens; 256 threads; 2 CTAs/SM; grid 4096.
__global__ void __launch_bounds__(256, 2) k012_fused(
    const float* __restrict__ x,
    const float* __restrict__ xstat,
    const float* __restrict__ xhres,
    const float* __restrict__ embed_w,
    const float* __restrict__ embed_b,
    const float* __restrict__ loan1_w,
    const float* __restrict__ loan1_b,
    const float* __restrict__ cw_f, const float* __restrict__ cb_f,
    const float* __restrict__ dtb_f, const float* __restrict__ al_f,
    const float* __restrict__ Dp_f, const float* __restrict__ nw_f,
    const float* __restrict__ cw_b, const float* __restrict__ cb_b,
    const float* __restrict__ dtb_b, const float* __restrict__ al_b,
    const float* __restrict__ Dp_b, const float* __restrict__ nw_b)
{
    extern __shared__ float smx[];
    float*    u_s = smx;                     // [64][268] fp32
    float*    ovl = smx + 64*268;            // overlay: As (GEMM) then xc0/xc1
    unsigned* As  = (unsigned*)ovl;          // [64][128] swizzled tf32
    float*    dtA = smx + 64*268 + 64*128;   // dt[2][240] dA[2][240]
    __shared__ float Aneg[2][8];

    const int blk  = blockIdx.x;
    const int b    = blk >> 11;
    const int tg   = (blk >> 10) & 1;
    const int qgrp = blk & 1023;
    const int tid  = threadIdx.x;
    const int warp = tid >> 5, lane = tid & 31;

    // ---- prologue: warp-per-token, 8 passes over 64 rows (60 real) ----
    for (int pass = 0; pass < 8; pass++) {
        const int m = pass*8 + warp;
        if (m < 60) {
            const int t_loc = m / 20;
            const int p_loc = m - t_loc*20;
            const int gi = (b*TT + tg*3 + t_loc)*PP + qgrp*20 + p_loc;
            const size_t base = (size_t)Goff[gi];

            float hval = (lane < 28) ? xhres[base*28 + lane] : 0.0f;
            float sval = (lane < 8)  ? xstat[base*8 + lane]  : 0.0f;

            const int j0 = (lane >= 24) ? (lane - 24) * 4 : 0;
            float a0 = embed_b[j0], a1 = embed_b[j0+1], a2 = embed_b[j0+2], a3 = embed_b[j0+3];
            #pragma unroll
            for (int k = 0; k < 28; k++) {
                float hk = __shfl_sync(0xffffffffu, hval, k);
                a0 = fmaf(hk, embed_w[k*32 + j0    ], a0);
                a1 = fmaf(hk, embed_w[k*32 + j0 + 1], a1);
                a2 = fmaf(hk, embed_w[k*32 + j0 + 2], a2);
                a3 = fmaf(hk, embed_w[k*32 + j0 + 3], a3);
            }
            float v0, v1, v2, v3;
            if (lane < 24) {
                float4 xv = *(const float4*)(x + base*96 + lane*4);
                v0 = xv.x; v1 = xv.y; v2 = xv.z; v3 = xv.w;
            } else {
                v0 = tanhf(a0); v1 = tanhf(a1); v2 = tanhf(a2); v3 = tanhf(a3);
            }
            float s1 = v0+v1+v2+v3;
            float s2 = v0*v0+v1*v1+v2*v2+v3*v3;
            #pragma unroll
            for (int o = 16; o > 0; o >>= 1) {
                s1 += __shfl_xor_sync(0xffffffffu, s1, o);
                s2 += __shfl_xor_sync(0xffffffffu, s2, o);
            }
            float mu  = s1 * (1.0f/128.0f);
            float var = s2 * (1.0f/128.0f) - mu*mu;
            float rs  = rsqrtf(var + 1e-5f);
            float sv[8];
            #pragma unroll
            for (int k = 0; k < 8; k++) sv[k] = __shfl_sync(0xffffffffu, sval, k);
            const int c = lane*4;
            float o0 = loan1_b[c], o1 = loan1_b[c+1], o2 = loan1_b[c+2], o3 = loan1_b[c+3];
            #pragma unroll
            for (int k = 0; k < 8; k++) {
                o0 = fmaf(sv[k], loan1_w[k*128 + c    ], o0);
                o1 = fmaf(sv[k], loan1_w[k*128 + c + 1], o1);
                o2 = fmaf(sv[k], loan1_w[k*128 + c + 2], o2);
                o3 = fmaf(sv[k], loan1_w[k*128 + c + 3], o3);
            }
            o0 = (v0 - mu)*rs + tanhf(o0);
            o1 = (v1 - mu)*rs + tanhf(o1);
            o2 = (v2 - mu)*rs + tanhf(o2);
            o3 = (v3 - mu)*rs + tanhf(o3);
            stage4(As + m*128, (m&1)<<4, lane, o0, o1, o2, o3);
        } else {
            stage4(As + m*128, (m&1)<<4, lane, 0.f, 0.f, 0.f, 0.f);
        }
    }
    __syncthreads();

    // ---- GEMM: u = xn @ Wp1, M=64, K=128, into u_s (N=288 trim) ----
    {
        const int gid = lane >> 2, tq = lane & 3;
        const int wm = warp & 1, wn = warp >> 1;

        // chunk0: cols 0..159
        {
            float acc[2][5][4] = {};
            #pragma unroll
            for (int it = 0; it < 8; it++) {
                const int cb = it*16 + tq*4;
                uint4 a0v[2], a8v[2], bv[5];
                #pragma unroll
                for (int mt = 0; mt < 2; mt++) {
                    int r0 = wm*32 + mt*16 + gid;
                    int sw = (r0 & 1) << 4;
                    a0v[mt] = *(const uint4*)(As + r0*128 + (cb ^ sw));
                    a8v[mt] = *(const uint4*)(As + (r0+8)*128 + (cb ^ sw));
                }
                #pragma unroll
                for (int nt = 0; nt < 5; nt++) {
                    int nr = wn*40 + nt*8 + gid;
                    bv[nt] = *(const uint4*)(Wp1 + nr*128 + cb);
                }
                #pragma unroll
                for (int mt = 0; mt < 2; mt++) {
                    #pragma unroll
                    for (int nt = 0; nt < 5; nt++) {
                        unsigned aa1[4] = {a0v[mt].x, a8v[mt].x, a0v[mt].y, a8v[mt].y};
                        unsigned bb1[2] = {bv[nt].x, bv[nt].y};
                        mma_tf32(acc[mt][nt], aa1, bb1);
                        unsigned aa2[4] = {a0v[mt].z, a8v[mt].z, a0v[mt].w, a8v[mt].w};
                        unsigned bb2[2] = {bv[nt].z, bv[nt].w};
                        mma_tf32(acc[mt][nt], aa2, bb2);
                    }
                }
            }
            #pragma unroll
            for (int mt = 0; mt < 2; mt++) {
                int row = wm*32 + mt*16 + gid;
                #pragma unroll
                for (int nt = 0; nt < 5; nt++) {
                    int col = wn*40 + nt*8 + tq*2;
                    *(float2*)(u_s + row*268 + col) =
                        make_float2(acc[mt][nt][0], acc[mt][nt][1]);
                    *(float2*)(u_s + (row+8)*268 + col) =
                        make_float2(acc[mt][nt][2], acc[mt][nt][3]);
                }
            }
        }
        // chunk1: cols 160..287 (only 160..265 stored)
        {
            float acc[2][4][4] = {};
            #pragma unroll
            for (int it = 0; it < 8; it++) {
                const int cb = it*16 + tq*4;
                uint4 a0v[2], a8v[2], bv[4];
                #pragma unroll
                for (int mt = 0; mt < 2; mt++) {
                    int r0 = wm*32 + mt*16 + gid;
                    int sw = (r0 & 1) << 4;
                    a0v[mt] = *(const uint4*)(As + r0*128 + (cb ^ sw));
                    a8v[mt] = *(const uint4*)(As + (r0+8)*128 + (cb ^ sw));
                }
                #pragma unroll
                for (int nt = 0; nt < 4; nt++) {
                    int nr = 160 + wn*32 + nt*8 + gid;
                    bv[nt] = *(const uint4*)(Wp1 + nr*128 + cb);
                }
                #pragma unroll
                for (int mt = 0; mt < 2; mt++) {
                    #pragma unroll
                    for (int nt = 0; nt < 4; nt++) {
                        unsigned aa1[4] = {a0v[mt].x, a8v[mt].x, a0v[mt].y, a8v[mt].y};
                        unsigned bb1[2] = {bv[nt].x, bv[nt].y};
                        mma_tf32(acc[mt][nt], aa1, bb1);
                        unsigned aa2[4] = {a0v[mt].z, a8v[mt].z, a0v[mt].w, a8v[mt].w};
                        unsigned bb2[2] = {bv[nt].z, bv[nt].w};
                        mma_tf32(acc[mt][nt], aa2, bb2);
                    }
                }
            }
            #pragma unroll
            for (int mt = 0; mt < 2; mt++) {
                int row = wm*32 + mt*16 + gid;
                #pragma unroll
                for (int nt = 0; nt < 4; nt++) {
                    int col = 160 + wn*32 + nt*8 + tq*2;
                    if (col < DPROJ) {
                        *(float2*)(u_s + row*268 + col) =
                            make_float2(acc[mt][nt][0], acc[mt][nt][1]);
                        *(float2*)(u_s + (row+8)*268 + col) =
                            make_float2(acc[mt][nt][2], acc[mt][nt][3]);
                    }
                }
            }
        }
    }
    if (tid < 16) Aneg[tid>>3][tid&7] = -expf((tid < 8 ? al_f : al_b)[tid & 7]);
    __syncthreads();   // u_s complete; As region free -> xc overlay

    // ---- mamba: 2 rounds (fwd, bwd); group g = seq (qg = qgrp*2+g) ----
    const int g  = tid >> 7;
    const int lt = tid & 127;
    float* xcg = ovl + g*3960;           // [30][132]
    float* dts = dtA + g*240;
    float* dAs = dtA + 480 + g*240;
    const int qg_src = qgrp*2 + g;

    #pragma unroll
    for (int r = 0; r < 2; r++) {
        const float* conv_w = r ? cw_b  : cw_f;
        const float* conv_b = r ? cb_b  : cb_f;
        const float* dtbp   = r ? dtb_b : dtb_f;
        const float* Dpp    = r ? Dp_b  : Dp_f;

        // dt = softplus(raw+bias), dA = exp(dt*A)  (fast-math exp)
        for (int i = lt; i < 240; i += 128) {
            int l = i >> 3, h = i & 7;
            int l10 = l / 10, lr = l - l10*10;
            int lu_r = r ? (9 - lr) : lr;
            int mu_ = l10*20 + g*10 + lu_r;
            float raw = u_s[mu_*268 + 258 + h] + dtbp[h];
            float dt = (raw > 20.f) ? raw : log1pf(__expf(raw));
            dts[l*8 + h] = dt;
            dAs[l*8 + h] = __expf(dt * Aneg[r][h]);
        }
        // causal depthwise conv + silu: ONE pass; threads 0,1 also do B/C channels
        {
            const int c = lt;
            float w0 = conv_w[c*3+0], w1 = conv_w[c*3+1], w2 = conv_w[c*3+2];
            float bias = conv_b[c];
            float p2 = 0.f, p1 = 0.f;
            const bool dual = (lt < 2);
            const int c2 = 128 + lt;
            float w0b = 0.f, w1b = 0.f, w2b = 0.f, biasb = 0.f;
            float q2 = 0.f, q1 = 0.f;
            if (dual) {
                w0b = conv_w[c2*3+0]; w1b = conv_w[c2*3+1]; w2b = conv_w[c2*3+2];
                biasb = conv_b[c2];
            }
            #pragma unroll
            for (int l = 0; l < 30; l++) {
                int l10 = l / 10, lr = l - l10*10;
                int mu_ = l10*20 + g*10 + (r ? (9 - lr) : lr);
                float v = u_s[mu_*268 + 128 + c];
                float a = fmaf(p2, w0, fmaf(p1, w1, fmaf(v, w2, bias)));
                xcg[l*132 + c] = __fdividef(a, 1.f + __expf(-a));
                p2 = p1; p1 = v;
                if (dual) {
                    float vb = u_s[mu_*268 + 128 + c2];
                    float ab = fmaf(q2, w0b, fmaf(q1, w1b, fmaf(vb, w2b, biasb)));
                    xcg[l*132 + c2] = __fdividef(ab, 1.f + __expf(-ab));
                    q2 = q1; q1 = vb;
                }
            }
        }
        __syncthreads();

        // scalar scan; y overlays xc column c (fast-math silu gate)
        {
            const int c = lt, h = c >> 4;
            const float Dh = Dpp[h];
            float hs = 0.f;
            #pragma unroll
            for (int l = 0; l < 30; l++) {
                int l10 = l / 10, lr = l - l10*10;
                int mu_ = l10*20 + g*10 + (r ? (9 - lr) : lr);
                float xv = xcg[l*132 + c];
                float Bv = xcg[l*132 + 128];
                float Cv = xcg[l*132 + 129];
                hs = fmaf(hs, dAs[l*8+h], dts[l*8+h]*xv*Bv);
                float y = fmaf(hs, Cv, xv*Dh);
                float z = u_s[mu_*268 + c];
                y *= __fdividef(z, 1.f + __expf(-z));
                xcg[l*132 + c] = y;
            }
        }
        __syncthreads();

        // RMS + scatter
        {
            const int w4 = warp & 3;
            const float* nww = r ? nw_b : nw_f;
            float* ybuf = r ? S_yb : S_yf;
            const int qgu = r ? (2047 - qg_src) : qg_src;
            const int abase = (tg*1024 + (qgu>>1))*6 + (qgu&1);
            for (int l = w4; l < 30; l += 4) {
                float4 v = *(float4*)(xcg + l*132 + lane*4);
                float ss = v.x*v.x + v.y*v.y + v.z*v.z + v.w*v.w;
                #pragma unroll
                for (int o = 16; o > 0; o >>= 1) ss += __shfl_xor_sync(0xffffffffu, ss, o);
                float scale = rsqrtf(ss*(1.f/128.f) + 1e-5f) * 0.5f;
                int l3 = l / 3;
                int f = l3*12288 + abase + (l - l3*3)*2;
                int t_out = f / PP;
                int p_out = f - t_out*PP;
                if (r) p_out = PP-1 - p_out;
                float4 w = *(const float4*)(nww + lane*4);
                float4 o;
                o.x = v.x*scale*w.x; o.y = v.y*scale*w.y;
                o.z = v.z*scale*w.z; o.w = v.w*scale*w.w;
                *(float4*)(ybuf + ((size_t)(b*TT + t_out)*PP + p_out)*128 + lane*4) = o;
            }
        }
        __syncthreads();
    }
}

// ===== GEMM helper: M64xN96, A in smem, B via LDG =====
template<int KIT, int KSTRIDE>
__device__ __forceinline__ void gemm_ldgB(const unsigned* __restrict__ Ab, int SA,
                                          const unsigned* __restrict__ Wg,
                                          int wm, int wn, int gid, int tq,
                                          float (&acc)[2][3][4])
{
    #pragma unroll
    for (int it = 0; it < KIT; it++) {
        const int cb = it*16 + tq*4;
        uint4 a0v[2], a8v[2], bv[3];
        #pragma unroll
        for (int mt = 0; mt < 2; mt++) {
            int r0 = wm*32 + mt*16 + gid;
            int sw = (r0 & 1) << 4;
            a0v[mt] = *(const uint4*)(Ab + r0*SA + (cb ^ sw));
            a8v[mt] = *(const uint4*)(Ab + (r0+8)*SA + (cb ^ sw));
        }
        #pragma unroll
        for (int nt = 0; nt < 3; nt++) {
            int nr = wn*24 + nt*8 + gid;
            bv[nt] = *(const uint4*)(Wg + nr*KSTRIDE + cb);
        }
        #pragma unroll
        for (int mt = 0; mt < 2; mt++) {
            #pragma unroll
            for (int nt = 0; nt < 3; nt++) {
                unsigned aa1[4] = {a0v[mt].x, a8v[mt].x, a0v[mt].y, a8v[mt].y};
                unsigned bb1[2] = {bv[nt].x, bv[nt].y};
                mma_tf32(acc[mt][nt], aa1, bb1);
                unsigned aa2[4] = {a0v[mt].z, a8v[mt].z, a0v[mt].w, a8v[mt].w};
                unsigned bb2[2] = {bv[nt].z, bv[nt].w};
                mma_tf32(acc[mt][nt], aa2, bb2);
            }
        }
    }
}

// ================= K34: out_proj + residual + LN + loan2 + MLP, fused (R5) ==========
__global__ void __launch_bounds__(256, 3) k34_fused(
    const float* __restrict__ x,
    const float* __restrict__ xstat,
    const float* __restrict__ loan2_w,
    const float* __restrict__ loan2_b,
    const float* __restrict__ b1,
    const float* __restrict__ b2,
    float* __restrict__ out)
{
    extern __shared__ unsigned smf[];
    unsigned* As  = smf;                     // [64][128]; tts/hs overlay
    float*    x1s = (float*)(smf + 64*128);  // [64][100]
    unsigned* tts = As;
    unsigned* hs  = As;

    const int tid = threadIdx.x;
    const int m_base = blockIdx.x * 64;
    const int warp = tid >> 5, lane = tid & 31;
    const int gid = lane >> 2, tq = lane & 3;
    const int wm = warp & 1, wn = warp >> 1;

    for (int i = tid; i < 64*32; i += 256) {
        int m = i >> 5, c = i & 31;
        size_t off = (size_t)(m_base+m)*128 + c*4;
        float4 a = *(const float4*)(S_yf + off);
        float4 q = *(const float4*)(S_yb + off);
        stage4(As + m*128, (m&1)<<4, c, a.x+q.x, a.y+q.y, a.z+q.z, a.w+q.w);
    }
    __syncthreads();

    float acc[2][3][4] = {};
    gemm_ldgB<8,128>(As, 128, WoP, wm, wn, gid, tq, acc);

    #pragma unroll
    for (int mt = 0; mt < 2; mt++) {
        int r = wm*32 + mt*16 + gid;
        #pragma unroll
        for (int nt = 0; nt < 3; nt++) {
            int c = wn*24 + nt*8 + tq*2;
            x1s[r*100 + c]     = acc[mt][nt][0];
            x1s[r*100 + c + 1] = acc[mt][nt][1];
            x1s[(r+8)*100 + c]     = acc[mt][nt][2];
            x1s[(r+8)*100 + c + 1] = acc[mt][nt][3];
        }
    }
    __syncthreads();

    for (int r = warp; r < 64; r += 8) {
        int gm = m_base + r;
        size_t base = (size_t)Goff[gm];
        size_t xb = base*96;
        float v0 = x1s[r*100 + lane*3 + 0] + x[xb + lane*3 + 0];
        float v1 = x1s[r*100 + lane*3 + 1] + x[xb + lane*3 + 1];
        float v2 = x1s[r*100 + lane*3 + 2] + x[xb + lane*3 + 2];
        x1s[r*100 + lane*3 + 0] = v0;
        x1s[r*100 + lane*3 + 1] = v1;
        x1s[r*100 + lane*3 + 2] = v2;
        float s1 = v0+v1+v2, s2 = v0*v0+v1*v1+v2*v2;
        #pragma unroll
        for (int o = 16; o > 0; o >>= 1) {
            s1 += __shfl_xor_sync(0xffffffffu, s1, o);
            s2 += __shfl_xor_sync(0xffffffffu, s2, o);
        }
        float mu  = s1 * (1.0f/96.0f);
        float var = s2 * (1.0f/96.0f) - mu*mu;
        float rs  = rsqrtf(var + 1e-5f);
        size_t sbase = base*8;
        float xs[8];
        #pragma unroll
        for (int k = 0; k < 8; k++) xs[k] = xstat[sbase + k];
        int swr = (r & 1) << 4;
        #pragma unroll
        for (int i2 = 0; i2 < 3; i2++) {
            int jj = lane*3 + i2;
            float a = loan2_b[jj];
            #pragma unroll
            for (int k = 0; k < 8; k++) a = fmaf(xs[k], loan2_w[k*96 + jj], a);
            float vv = (i2 == 0) ? v0 : ((i2 == 1) ? v1 : v2);
            tts[r*96 + (kperm16(jj) ^ swr)] = f2tf32((vv - mu)*rs + tanhf(a));
        }
    }
    __syncthreads();

    float acc1[2][3][4] = {};
    gemm_ldgB<6,96>(tts, 96, W1P, wm, wn, gid, tq, acc1);
    __syncthreads();

    #pragma unroll
    for (int mt = 0; mt < 2; mt++) {
        int r = wm*32 + mt*16 + gid;
        int swr = (r & 1) << 4;
        #pragma unroll
        for (int nt = 0; nt < 3; nt++) {
            int c = wn*24 + nt*8 + tq*2;
            float bb0 = b1[c], bb1 = b1[c+1];
            hs[r*96 + (kperm16(c)   ^ swr)] = f2tf32(geluf(acc1[mt][nt][0] + bb0));
            hs[r*96 + (kperm16(c+1) ^ swr)] = f2tf32(geluf(acc1[mt][nt][1] + bb1));
            hs[(r+8)*96 + (kperm16(c)   ^ swr)] = f2tf32(geluf(acc1[mt][nt][2] + bb0));
            hs[(r+8)*96 + (kperm16(c+1) ^ swr)] = f2tf32(geluf(acc1[mt][nt][3] + bb1));
        }
    }
    __syncthreads();

    float acc2[2][3][4] = {};
    gemm_ldgB<6,96>(hs, 96, W2P, wm, wn, gid, tq, acc2);

    #pragma unroll
    for (int mt = 0; mt < 2; mt++) {
        int r = wm*32 + mt*16 + gid;
        int gm0 = m_base + r, gm8 = gm0 + 8;
        #pragma unroll
        for (int nt = 0; nt < 3; nt++) {
            int c = wn*24 + nt*8 + tq*2;
            float bb0 = b2[c], bb1 = b2[c+1];
            *(float2*)(out + (size_t)gm0*96 + c) = make_float2(
                acc2[mt][nt][0] + bb0 + x1s[r*100 + c],
                acc2[mt][nt][1] + bb1 + x1s[r*100 + c + 1]);
            *(float2*)(out + (size_t)gm8*96 + c) = make_float2(
                acc2[mt][nt][2] + bb0 + x1s[(r+8)*100 + c],
                acc2[mt][nt][3] + bb1 + x1s[(r+8)*100 + c + 1]);
        }
    }
}

// ================= launcher =================
extern "C" void kernel_launch(void* const* d_in, const int* in_sizes, int n_in,
                              void* d_out, int out_size)
{
    const float* x       = (const float*)d_in[0];
    const float* xstat   = (const float*)d_in[1];
    const float* xhres   = (const float*)d_in[2];
    const int*   curves  = (const int*)  d_in[3];
    const float* embed_w = (const float*)d_in[4];
    const float* embed_b = (const float*)d_in[5];
    const float* loan1_w = (const float*)d_in[6];
    const float* loan1_b = (const float*)d_in[7];
    const float* loan2_w = (const float*)d_in[8];
    const float* loan2_b = (const float*)d_in[9];
    const float* in_proj = (const float*)d_in[10];
    const float* cw_f  = (const float*)d_in[11];
    const float* cb_f  = (const float*)d_in[12];
    const float* dtb_f = (const float*)d_in[13];
    const float* al_f  = (const float*)d_in[14];
    const float* Dp_f  = (const float*)d_in[15];
    const float* nw_f  = (const float*)d_in[16];
    const float* cw_b  = (const float*)d_in[17];
    const float* cb_b  = (const float*)d_in[18];
    const float* dtb_b = (const float*)d_in[19];
    const float* al_b  = (const float*)d_in[20];
    const float* Dp_b  = (const float*)d_in[21];
    const float* nw_b  = (const float*)d_in[22];
    const float* Wo    = (const float*)d_in[23];
    const float* W1    = (const float*)d_in[24];
    const float* b1    = (const float*)d_in[25];
    const float* W2    = (const float*)d_in[26];
    const float* b2    = (const float*)d_in[27];
    float* out = (float*)d_out;

    const int smem012 = (64*268 + 64*128 + 960) * 4;   // 105216
    const int smem34  = (64*128 + 64*100) * 4;         // 58368

    cudaFuncSetAttribute(k012_fused, cudaFuncAttributeMaxDynamicSharedMemorySize, smem012);
    cudaFuncSetAttribute(k34_fused,  cudaFuncAttributeMaxDynamicSharedMemorySize, smem34);

    kprep<<<NTOK/256, 256>>>(in_proj, Wo, W1, W2, curves);

    k012_fused<<<4096, 256, smem012>>>(x, xstat, xhres,
                                       embed_w, embed_b, loan1_w, loan1_b,
                                       cw_f, cb_f, dtb_f, al_f, Dp_f, nw_f,
                                       cw_b, cb_b, dtb_b, al_b, Dp_b, nw_b);

    k34_fused<<<NTOK/64, 256, smem34>>>(x, xstat, loan2_w, loan2_b, b1, b2, out);
}

// round 13
// speedup vs baseline: 1.4234x; 1.0139x over previous
#include <cuda_runtime.h>
#include <math.h>

#define BB 2
#define TT 6
#define PP 20480
#define NTOK (BB*TT*PP)      /* 245760 */
#define DPROJ 266

// ---------------- scratch ----------------
__device__ float S_yf[(size_t)NTOK*128];
__device__ float S_yb[(size_t)NTOK*128];
__device__ int   Goff[NTOK];
// pre-permuted tf32 weights (B operands, n-major, kperm16'd)
__device__ unsigned Wp1[320*128];
__device__ unsigned WoP[96*128];
__device__ unsigned W1P[96*96];
__device__ unsigned W2P[96*96];

__device__ __forceinline__ float geluf(float v) {
    return 0.5f * v * (1.0f + erff(v * 0.70710678118654752f));
}
// fast tanh: 1 - 2/(e^{2x}+1); saturates correctly at +-inf, abs err ~1e-5
__device__ __forceinline__ float ftanh(float x) {
    float e = __expf(2.0f * x);
    return 1.0f - __fdividef(2.0f, e + 1.0f);
}
__device__ __forceinline__ unsigned f2tf32(float f) {
    unsigned r;
    asm("cvt.rna.tf32.f32 %0, %1;" : "=r"(r) : "f"(f));
    return r;
}
__device__ __forceinline__ int kperm16(int k) {
    int g = k & ~15, j = k & 15;
    return g + ((j & 3) << 2) + (j >> 2);
}
__device__ __forceinline__ void mma_tf32(float* c, const unsigned* a, const unsigned* b) {
    asm volatile(
        "mma.sync.aligned.m16n8k8.row.col.f32.tf32.tf32.f32 "
        "{%0,%1,%2,%3}, {%4,%5,%6,%7}, {%8,%9}, {%0,%1,%2,%3};"
        : "+f"(c[0]), "+f"(c[1]), "+f"(c[2]), "+f"(c[3])
        : "r"(a[0]), "r"(a[1]), "r"(a[2]), "r"(a[3]), "r"(b[0]), "r"(b[1]));
}
__device__ __forceinline__ void stage4(unsigned* row, int sw, int c, float x, float y, float z, float w) {
    int g = (c >> 2) << 4, r = c & 3;
    row[(g + r     ) ^ sw] = f2tf32(x);
    row[(g + r + 4 ) ^ sw] = f2tf32(y);
    row[(g + r + 8 ) ^ sw] = f2tf32(z);
    row[(g + r + 12) ^ sw] = f2tf32(w);
}

// ================= prep: weights + gather offsets =================
__global__ void kprep(const float* __restrict__ inproj, const float* __restrict__ Wo,
                      const float* __restrict__ W1, const float* __restrict__ W2,
                      const int* __restrict__ curves)
{
    int i = blockIdx.x * 256 + threadIdx.x;
    if (i < 320*128) {
        int n = i >> 7, k = i & 127;
        float v = (n < DPROJ) ? inproj[(size_t)k*DPROJ + n] : 0.0f;
        Wp1[n*128 + kperm16(k)] = f2tf32(v);
    }
    if (i < 96*128) {
        int n = i >> 7, k = i & 127;
        WoP[n*128 + kperm16(k)] = f2tf32(Wo[(size_t)k*96 + n]);
    }
    if (i < 96*96) {
        int n = i / 96, k = i - n*96;
        W1P[n*96 + kperm16(k)] = f2tf32(W1[(size_t)k*96 + n]);
        W2P[n*96 + kperm16(k)] = f2tf32(W2[(size_t)k*96 + n]);
    }
    if (i < NTOK) {
        int b  = i / (TT*PP);
        int tp = i - b*TT*PP;
        int t  = tp / PP;
        int p  = tp - t*PP;
        Goff[i] = (b*TT + t)*PP + curves[b*PP + p];
    }
}

// ================= K012: prologue + in_proj GEMM + mamba =================
// R12 + fast tanh in prologue.
// CTA = (b, tg, qgrp): 60 tokens; 256 threads; 2 CTAs/SM; grid 4096.
__global__ void __launch_bounds__(256, 2) k012_fused(
    const float* __restrict__ x,
    const float* __restrict__ xstat,
    const float* __restrict__ xhres,
    const float* __restrict__ embed_w,
    const float* __restrict__ embed_b,
    const float* __restrict__ loan1_w,
    const float* __restrict__ loan1_b,
    const float* __restrict__ cw_f, const float* __restrict__ cb_f,
    const float* __restrict__ dtb_f, const float* __restrict__ al_f,
    const float* __restrict__ Dp_f, const float* __restrict__ nw_f,
    const float* __restrict__ cw_b, const float* __restrict__ cb_b,
    const float* __restrict__ dtb_b, const float* __restrict__ al_b,
    const float* __restrict__ Dp_b, const float* __restrict__ nw_b)
{
    extern __shared__ float smx[];
    float*    u_s = smx;                     // [64][268] fp32
    float*    ovl = smx + 64*268;            // overlay: As (GEMM) then xc0/xc1
    unsigned* As  = (unsigned*)ovl;          // [64][128] swizzled tf32
    float*    dtA = smx + 64*268 + 64*128;   // dt[2][240] dA[2][240]
    __shared__ float Aneg[2][8];

    const int blk  = blockIdx.x;
    const int b    = blk >> 11;
    const int tg   = (blk >> 10) & 1;
    const int qgrp = blk & 1023;
    const int tid  = threadIdx.x;
    const int warp = tid >> 5, lane = tid & 31;

    // ---- prologue: warp-per-token, 8 passes over 64 rows (60 real) ----
    for (int pass = 0; pass < 8; pass++) {
        const int m = pass*8 + warp;
        if (m < 60) {
            const int t_loc = m / 20;
            const int p_loc = m - t_loc*20;
            const int gi = (b*TT + tg*3 + t_loc)*PP + qgrp*20 + p_loc;
            const size_t base = (size_t)Goff[gi];

            float hval = (lane < 28) ? xhres[base*28 + lane] : 0.0f;
            float sval = (lane < 8)  ? xstat[base*8 + lane]  : 0.0f;

            const int j0 = (lane >= 24) ? (lane - 24) * 4 : 0;
            float a0 = embed_b[j0], a1 = embed_b[j0+1], a2 = embed_b[j0+2], a3 = embed_b[j0+3];
            #pragma unroll
            for (int k = 0; k < 28; k++) {
                float hk = __shfl_sync(0xffffffffu, hval, k);
                a0 = fmaf(hk, embed_w[k*32 + j0    ], a0);
                a1 = fmaf(hk, embed_w[k*32 + j0 + 1], a1);
                a2 = fmaf(hk, embed_w[k*32 + j0 + 2], a2);
                a3 = fmaf(hk, embed_w[k*32 + j0 + 3], a3);
            }
            float v0, v1, v2, v3;
            if (lane < 24) {
                float4 xv = *(const float4*)(x + base*96 + lane*4);
                v0 = xv.x; v1 = xv.y; v2 = xv.z; v3 = xv.w;
            } else {
                v0 = ftanh(a0); v1 = ftanh(a1); v2 = ftanh(a2); v3 = ftanh(a3);
            }
            float s1 = v0+v1+v2+v3;
            float s2 = v0*v0+v1*v1+v2*v2+v3*v3;
            #pragma unroll
            for (int o = 16; o > 0; o >>= 1) {
                s1 += __shfl_xor_sync(0xffffffffu, s1, o);
                s2 += __shfl_xor_sync(0xffffffffu, s2, o);
            }
            float mu  = s1 * (1.0f/128.0f);
            float var = s2 * (1.0f/128.0f) - mu*mu;
            float rs  = rsqrtf(var + 1e-5f);
            float sv[8];
            #pragma unroll
            for (int k = 0; k < 8; k++) sv[k] = __shfl_sync(0xffffffffu, sval, k);
            const int c = lane*4;
            float o0 = loan1_b[c], o1 = loan1_b[c+1], o2 = loan1_b[c+2], o3 = loan1_b[c+3];
            #pragma unroll
            for (int k = 0; k < 8; k++) {
                o0 = fmaf(sv[k], loan1_w[k*128 + c    ], o0);
                o1 = fmaf(sv[k], loan1_w[k*128 + c + 1], o1);
                o2 = fmaf(sv[k], loan1_w[k*128 + c + 2], o2);
                o3 = fmaf(sv[k], loan1_w[k*128 + c + 3], o3);
            }
            o0 = (v0 - mu)*rs + ftanh(o0);
            o1 = (v1 - mu)*rs + ftanh(o1);
            o2 = (v2 - mu)*rs + ftanh(o2);
            o3 = (v3 - mu)*rs + ftanh(o3);
            stage4(As + m*128, (m&1)<<4, lane, o0, o1, o2, o3);
        } else {
            stage4(As + m*128, (m&1)<<4, lane, 0.f, 0.f, 0.f, 0.f);
        }
    }
    __syncthreads();

    // ---- GEMM: u = xn @ Wp1, M=64, K=128, into u_s (N=288 trim) ----
    {
        const int gid = lane >> 2, tq = lane & 3;
        const int wm = warp & 1, wn = warp >> 1;

        // chunk0: cols 0..159
        {
            float acc[2][5][4] = {};
            #pragma unroll
            for (int it = 0; it < 8; it++) {
                const int cb = it*16 + tq*4;
                uint4 a0v[2], a8v[2], bv[5];
                #pragma unroll
                for (int mt = 0; mt < 2; mt++) {
                    int r0 = wm*32 + mt*16 + gid;
                    int sw = (r0 & 1) << 4;
                    a0v[mt] = *(const uint4*)(As + r0*128 + (cb ^ sw));
                    a8v[mt] = *(const uint4*)(As + (r0+8)*128 + (cb ^ sw));
                }
                #pragma unroll
                for (int nt = 0; nt < 5; nt++) {
                    int nr = wn*40 + nt*8 + gid;
                    bv[nt] = *(const uint4*)(Wp1 + nr*128 + cb);
                }
                #pragma unroll
                for (int mt = 0; mt < 2; mt++) {
                    #pragma unroll
                    for (int nt = 0; nt < 5; nt++) {
                        unsigned aa1[4] = {a0v[mt].x, a8v[mt].x, a0v[mt].y, a8v[mt].y};
                        unsigned bb1[2] = {bv[nt].x, bv[nt].y};
                        mma_tf32(acc[mt][nt], aa1, bb1);
                        unsigned aa2[4] = {a0v[mt].z, a8v[mt].z, a0v[mt].w, a8v[mt].w};
                        unsigned bb2[2] = {bv[nt].z, bv[nt].w};
                        mma_tf32(acc[mt][nt], aa2, bb2);
                    }
                }
            }
            #pragma unroll
            for (int mt = 0; mt < 2; mt++) {
                int row = wm*32 + mt*16 + gid;
                #pragma unroll
                for (int nt = 0; nt < 5; nt++) {
                    int col = wn*40 + nt*8 + tq*2;
                    *(float2*)(u_s + row*268 + col) =
                        make_float2(acc[mt][nt][0], acc[mt][nt][1]);
                    *(float2*)(u_s + (row+8)*268 + col) =
                        make_float2(acc[mt][nt][2], acc[mt][nt][3]);
                }
            }
        }
        // chunk1: cols 160..287 (only 160..265 stored)
        {
            float acc[2][4][4] = {};
            #pragma unroll
            for (int it = 0; it < 8; it++) {
                const int cb = it*16 + tq*4;
                uint4 a0v[2], a8v[2], bv[4];
                #pragma unroll
                for (int mt = 0; mt < 2; mt++) {
                    int r0 = wm*32 + mt*16 + gid;
                    int sw = (r0 & 1) << 4;
                    a0v[mt] = *(const uint4*)(As + r0*128 + (cb ^ sw));
                    a8v[mt] = *(const uint4*)(As + (r0+8)*128 + (cb ^ sw));
                }
                #pragma unroll
                for (int nt = 0; nt < 4; nt++) {
                    int nr = 160 + wn*32 + nt*8 + gid;
                    bv[nt] = *(const uint4*)(Wp1 + nr*128 + cb);
                }
                #pragma unroll
                for (int mt = 0; mt < 2; mt++) {
                    #pragma unroll
                    for (int nt = 0; nt < 4; nt++) {
                        unsigned aa1[4] = {a0v[mt].x, a8v[mt].x, a0v[mt].y, a8v[mt].y};
                        unsigned bb1[2] = {bv[nt].x, bv[nt].y};
                        mma_tf32(acc[mt][nt], aa1, bb1);
                        unsigned aa2[4] = {a0v[mt].z, a8v[mt].z, a0v[mt].w, a8v[mt].w};
                        unsigned bb2[2] = {bv[nt].z, bv[nt].w};
                        mma_tf32(acc[mt][nt], aa2, bb2);
                    }
                }
            }
            #pragma unroll
            for (int mt = 0; mt < 2; mt++) {
                int row = wm*32 + mt*16 + gid;
                #pragma unroll
                for (int nt = 0; nt < 4; nt++) {
                    int col = 160 + wn*32 + nt*8 + tq*2;
                    if (col < DPROJ) {
                        *(float2*)(u_s + row*268 + col) =
                            make_float2(acc[mt][nt][0], acc[mt][nt][1]);
                        *(float2*)(u_s + (row+8)*268 + col) =
                            make_float2(acc[mt][nt][2], acc[mt][nt][3]);
                    }
                }
            }
        }
    }
    if (tid < 16) Aneg[tid>>3][tid&7] = -__expf((tid < 8 ? al_f : al_b)[tid & 7]);
    __syncthreads();   // u_s complete; As region free -> xc overlay

    // ---- mamba: 2 rounds (fwd, bwd); group g = seq (qg = qgrp*2+g) ----
    const int g  = tid >> 7;
    const int lt = tid & 127;
    float* xcg = ovl + g*3960;           // [30][132]
    float* dts = dtA + g*240;
    float* dAs = dtA + 480 + g*240;
    const int qg_src = qgrp*2 + g;

    #pragma unroll
    for (int r = 0; r < 2; r++) {
        const float* conv_w = r ? cw_b  : cw_f;
        const float* conv_b = r ? cb_b  : cb_f;
        const float* dtbp   = r ? dtb_b : dtb_f;
        const float* Dpp    = r ? Dp_b  : Dp_f;

        // dt = softplus(raw+bias), dA = exp(dt*A)  (fast-math exp)
        for (int i = lt; i < 240; i += 128) {
            int l = i >> 3, h = i & 7;
            int l10 = l / 10, lr = l - l10*10;
            int lu_r = r ? (9 - lr) : lr;
            int mu_ = l10*20 + g*10 + lu_r;
            float raw = u_s[mu_*268 + 258 + h] + dtbp[h];
            float dt = (raw > 20.f) ? raw : log1pf(__expf(raw));
            dts[l*8 + h] = dt;
            dAs[l*8 + h] = __expf(dt * Aneg[r][h]);
        }
        // causal depthwise conv + silu: ONE pass; threads 0,1 also do B/C channels
        {
            const int c = lt;
            float w0 = conv_w[c*3+0], w1 = conv_w[c*3+1], w2 = conv_w[c*3+2];
            float bias = conv_b[c];
            float p2 = 0.f, p1 = 0.f;
            const bool dual = (lt < 2);
            const int c2 = 128 + lt;
            float w0b = 0.f, w1b = 0.f, w2b = 0.f, biasb = 0.f;
            float q2 = 0.f, q1 = 0.f;
            if (dual) {
                w0b = conv_w[c2*3+0]; w1b = conv_w[c2*3+1]; w2b = conv_w[c2*3+2];
                biasb = conv_b[c2];
            }
            #pragma unroll
            for (int l = 0; l < 30; l++) {
                int l10 = l / 10, lr = l - l10*10;
                int mu_ = l10*20 + g*10 + (r ? (9 - lr) : lr);
                float v = u_s[mu_*268 + 128 + c];
                float a = fmaf(p2, w0, fmaf(p1, w1, fmaf(v, w2, bias)));
                xcg[l*132 + c] = __fdividef(a, 1.f + __expf(-a));
                p2 = p1; p1 = v;
                if (dual) {
                    float vb = u_s[mu_*268 + 128 + c2];
                    float ab = fmaf(q2, w0b, fmaf(q1, w1b, fmaf(vb, w2b, biasb)));
                    xcg[l*132 + c2] = __fdividef(ab, 1.f + __expf(-ab));
                    q2 = q1; q1 = vb;
                }
            }
        }
        __syncthreads();

        // scalar scan; y overlays xc column c (fast-math silu gate)
        {
            const int c = lt, h = c >> 4;
            const float Dh = Dpp[h];
            float hs = 0.f;
            #pragma unroll
            for (int l = 0; l < 30; l++) {
                int l10 = l / 10, lr = l - l10*10;
                int mu_ = l10*20 + g*10 + (r ? (9 - lr) : lr);
                float xv = xcg[l*132 + c];
                float Bv = xcg[l*132 + 128];
                float Cv = xcg[l*132 + 129];
                hs = fmaf(hs, dAs[l*8+h], dts[l*8+h]*xv*Bv);
                float y = fmaf(hs, Cv, xv*Dh);
                float z = u_s[mu_*268 + c];
                y *= __fdividef(z, 1.f + __expf(-z));
                xcg[l*132 + c] = y;
            }
        }
        __syncthreads();

        // RMS + scatter
        {
            const int w4 = warp & 3;
            const float* nww = r ? nw_b : nw_f;
            float* ybuf = r ? S_yb : S_yf;
            const int qgu = r ? (2047 - qg_src) : qg_src;
            const int abase = (tg*1024 + (qgu>>1))*6 + (qgu&1);
            for (int l = w4; l < 30; l += 4) {
                float4 v = *(float4*)(xcg + l*132 + lane*4);
                float ss = v.x*v.x + v.y*v.y + v.z*v.z + v.w*v.w;
                #pragma unroll
                for (int o = 16; o > 0; o >>= 1) ss += __shfl_xor_sync(0xffffffffu, ss, o);
                float scale = rsqrtf(ss*(1.f/128.f) + 1e-5f) * 0.5f;
                int l3 = l / 3;
                int f = l3*12288 + abase + (l - l3*3)*2;
                int t_out = f / PP;
                int p_out = f - t_out*PP;
                if (r) p_out = PP-1 - p_out;
                float4 w = *(const float4*)(nww + lane*4);
                float4 o;
                o.x = v.x*scale*w.x; o.y = v.y*scale*w.y;
                o.z = v.z*scale*w.z; o.w = v.w*scale*w.w;
                *(float4*)(ybuf + ((size_t)(b*TT + t_out)*PP + p_out)*128 + lane*4) = o;
            }
        }
        __syncthreads();
    }
}

// ===== GEMM helper: M64xN96, A in smem, B via LDG =====
template<int KIT, int KSTRIDE>
__device__ __forceinline__ void gemm_ldgB(const unsigned* __restrict__ Ab, int SA,
                                          const unsigned* __restrict__ Wg,
                                          int wm, int wn, int gid, int tq,
                                          float (&acc)[2][3][4])
{
    #pragma unroll
    for (int it = 0; it < KIT; it++) {
        const int cb = it*16 + tq*4;
        uint4 a0v[2], a8v[2], bv[3];
        #pragma unroll
        for (int mt = 0; mt < 2; mt++) {
            int r0 = wm*32 + mt*16 + gid;
            int sw = (r0 & 1) << 4;
            a0v[mt] = *(const uint4*)(Ab + r0*SA + (cb ^ sw));
            a8v[mt] = *(const uint4*)(Ab + (r0+8)*SA + (cb ^ sw));
        }
        #pragma unroll
        for (int nt = 0; nt < 3; nt++) {
            int nr = wn*24 + nt*8 + gid;
            bv[nt] = *(const uint4*)(Wg + nr*KSTRIDE + cb);
        }
        #pragma unroll
        for (int mt = 0; mt < 2; mt++) {
            #pragma unroll
            for (int nt = 0; nt < 3; nt++) {
                unsigned aa1[4] = {a0v[mt].x, a8v[mt].x, a0v[mt].y, a8v[mt].y};
                unsigned bb1[2] = {bv[nt].x, bv[nt].y};
                mma_tf32(acc[mt][nt], aa1, bb1);
                unsigned aa2[4] = {a0v[mt].z, a8v[mt].z, a0v[mt].w, a8v[mt].w};
                unsigned bb2[2] = {bv[nt].z, bv[nt].w};
                mma_tf32(acc[mt][nt], aa2, bb2);
            }
        }
    }
}

// ================= K34: out_proj + residual + LN + loan2 + MLP, fused ==========
// R5 shape + fast tanh
__global__ void __launch_bounds__(256, 3) k34_fused(
    const float* __restrict__ x,
    const float* __restrict__ xstat,
    const float* __restrict__ loan2_w,
    const float* __restrict__ loan2_b,
    const float* __restrict__ b1,
    const float* __restrict__ b2,
    float* __restrict__ out)
{
    extern __shared__ unsigned smf[];
    unsigned* As  = smf;                     // [64][128]; tts/hs overlay
    float*    x1s = (float*)(smf + 64*128);  // [64][100]
    unsigned* tts = As;
    unsigned* hs  = As;

    const int tid = threadIdx.x;
    const int m_base = blockIdx.x * 64;
    const int warp = tid >> 5, lane = tid & 31;
    const int gid = lane >> 2, tq = lane & 3;
    const int wm = warp & 1, wn = warp >> 1;

    for (int i = tid; i < 64*32; i += 256) {
        int m = i >> 5, c = i & 31;
        size_t off = (size_t)(m_base+m)*128 + c*4;
        float4 a = *(const float4*)(S_yf + off);
        float4 q = *(const float4*)(S_yb + off);
        stage4(As + m*128, (m&1)<<4, c, a.x+q.x, a.y+q.y, a.z+q.z, a.w+q.w);
    }
    __syncthreads();

    float acc[2][3][4] = {};
    gemm_ldgB<8,128>(As, 128, WoP, wm, wn, gid, tq, acc);

    #pragma unroll
    for (int mt = 0; mt < 2; mt++) {
        int r = wm*32 + mt*16 + gid;
        #pragma unroll
        for (int nt = 0; nt < 3; nt++) {
            int c = wn*24 + nt*8 + tq*2;
            x1s[r*100 + c]     = acc[mt][nt][0];
            x1s[r*100 + c + 1] = acc[mt][nt][1];
            x1s[(r+8)*100 + c]     = acc[mt][nt][2];
            x1s[(r+8)*100 + c + 1] = acc[mt][nt][3];
        }
    }
    __syncthreads();

    for (int r = warp; r < 64; r += 8) {
        int gm = m_base + r;
        size_t base = (size_t)Goff[gm];
        size_t xb = base*96;
        float v0 = x1s[r*100 + lane*3 + 0] + x[xb + lane*3 + 0];
        float v1 = x1s[r*100 + lane*3 + 1] + x[xb + lane*3 + 1];
        float v2 = x1s[r*100 + lane*3 + 2] + x[xb + lane*3 + 2];
        x1s[r*100 + lane*3 + 0] = v0;
        x1s[r*100 + lane*3 + 1] = v1;
        x1s[r*100 + lane*3 + 2] = v2;
        float s1 = v0+v1+v2, s2 = v0*v0+v1*v1+v2*v2;
        #pragma unroll
        for (int o = 16; o > 0; o >>= 1) {
            s1 += __shfl_xor_sync(0xffffffffu, s1, o);
            s2 += __shfl_xor_sync(0xffffffffu, s2, o);
        }
        float mu  = s1 * (1.0f/96.0f);
        float var = s2 * (1.0f/96.0f) - mu*mu;
        float rs  = rsqrtf(var + 1e-5f);
        size_t sbase = base*8;
        float xs[8];
        #pragma unroll
        for (int k = 0; k < 8; k++) xs[k] = xstat[sbase + k];
        int swr = (r & 1) << 4;
        #pragma unroll
        for (int i2 = 0; i2 < 3; i2++) {
            int jj = lane*3 + i2;
            float a = loan2_b[jj];
            #pragma unroll
            for (int k = 0; k < 8; k++) a = fmaf(xs[k], loan2_w[k*96 + jj], a);
            float vv = (i2 == 0) ? v0 : ((i2 == 1) ? v1 : v2);
            tts[r*96 + (kperm16(jj) ^ swr)] = f2tf32((vv - mu)*rs + ftanh(a));
        }
    }
    __syncthreads();

    float acc1[2][3][4] = {};
    gemm_ldgB<6,96>(tts, 96, W1P, wm, wn, gid, tq, acc1);
    __syncthreads();

    #pragma unroll
    for (int mt = 0; mt < 2; mt++) {
        int r = wm*32 + mt*16 + gid;
        int swr = (r & 1) << 4;
        #pragma unroll
        for (int nt = 0; nt < 3; nt++) {
            int c = wn*24 + nt*8 + tq*2;
            float bb0 = b1[c], bb1 = b1[c+1];
            hs[r*96 + (kperm16(c)   ^ swr)] = f2tf32(geluf(acc1[mt][nt][0] + bb0));
            hs[r*96 + (kperm16(c+1) ^ swr)] = f2tf32(geluf(acc1[mt][nt][1] + bb1));
            hs[(r+8)*96 + (kperm16(c)   ^ swr)] = f2tf32(geluf(acc1[mt][nt][2] + bb0));
            hs[(r+8)*96 + (kperm16(c+1) ^ swr)] = f2tf32(geluf(acc1[mt][nt][3] + bb1));
        }
    }
    __syncthreads();

    float acc2[2][3][4] = {};
    gemm_ldgB<6,96>(hs, 96, W2P, wm, wn, gid, tq, acc2);

    #pragma unroll
    for (int mt = 0; mt < 2; mt++) {
        int r = wm*32 + mt*16 + gid;
        int gm0 = m_base + r, gm8 = gm0 + 8;
        #pragma unroll
        for (int nt = 0; nt < 3; nt++) {
            int c = wn*24 + nt*8 + tq*2;
            float bb0 = b2[c], bb1 = b2[c+1];
            *(float2*)(out + (size_t)gm0*96 + c) = make_float2(
                acc2[mt][nt][0] + bb0 + x1s[r*100 + c],
                acc2[mt][nt][1] + bb1 + x1s[r*100 + c + 1]);
            *(float2*)(out + (size_t)gm8*96 + c) = make_float2(
                acc2[mt][nt][2] + bb0 + x1s[(r+8)*100 + c],
                acc2[mt][nt][3] + bb1 + x1s[(r+8)*100 + c + 1]);
        }
    }
}

// ================= launcher =================
extern "C" void kernel_launch(void* const* d_in, const int* in_sizes, int n_in,
                              void* d_out, int out_size)
{
    const float* x       = (const float*)d_in[0];
    const float* xstat   = (const float*)d_in[1];
    const float* xhres   = (const float*)d_in[2];
    const int*   curves  = (const int*)  d_in[3];
    const float* embed_w = (const float*)d_in[4];
    const float* embed_b = (const float*)d_in[5];
    const float* loan1_w = (const float*)d_in[6];
    const float* loan1_b = (const float*)d_in[7];
    const float* loan2_w = (const float*)d_in[8];
    const float* loan2_b = (const float*)d_in[9];
    const float* in_proj = (const float*)d_in[10];
    const float* cw_f  = (const float*)d_in[11];
    const float* cb_f  = (const float*)d_in[12];
    const float* dtb_f = (const float*)d_in[13];
    const float* al_f  = (const float*)d_in[14];
    const float* Dp_f  = (const float*)d_in[15];
    const float* nw_f  = (const float*)d_in[16];
    const float* cw_b  = (const float*)d_in[17];
    const float* cb_b  = (const float*)d_in[18];
    const float* dtb_b = (const float*)d_in[19];
    const float* al_b  = (const float*)d_in[20];
    const float* Dp_b  = (const float*)d_in[21];
    const float* nw_b  = (const float*)d_in[22];
    const float* Wo    = (const float*)d_in[23];
    const float* W1    = (const float*)d_in[24];
    const float* b1    = (const float*)d_in[25];
    const float* W2    = (const float*)d_in[26];
    const float* b2    = (const float*)d_in[27];
    float* out = (float*)d_out;

    const int smem012 = (64*268 + 64*128 + 960) * 4;   // 105216
    const int smem34  = (64*128 + 64*100) * 4;         // 58368

    cudaFuncSetAttribute(k012_fused, cudaFuncAttributeMaxDynamicSharedMemorySize, smem012);
    cudaFuncSetAttribute(k34_fused,  cudaFuncAttributeMaxDynamicSharedMemorySize, smem34);

    kprep<<<NTOK/256, 256>>>(in_proj, Wo, W1, W2, curves);

    k012_fused<<<4096, 256, smem012>>>(x, xstat, xhres,
                                       embed_w, embed_b, loan1_w, loan1_b,
                                       cw_f, cb_f, dtb_f, al_f, Dp_f, nw_f,
                                       cw_b, cb_b, dtb_b, al_b, Dp_b, nw_b);

    k34_fused<<<NTOK/64, 256, smem34>>>(x, xstat, loan2_w, loan2_b, b1, b2, out);
}

// round 14
// speedup vs baseline: 1.5142x; 1.0638x over previous
#include <cuda_runtime.h>
#include <math.h>

#define BB 2
#define TT 6
#define PP 20480
#define NTOK (BB*TT*PP)      /* 245760 */
#define DPROJ 266

// ---------------- scratch ----------------
__device__ float S_yf[(size_t)NTOK*128];
__device__ float S_yb[(size_t)NTOK*128];
__device__ int   Goff[NTOK];
__device__ float Hr[(size_t)NTOK*32];   // precomputed tanh(xh@embed_w+b), 31.5 MB
// pre-permuted tf32 weights (B operands, n-major, kperm16'd)
__device__ unsigned Wp1[320*128];
__device__ unsigned WoP[96*128];
__device__ unsigned W1P[96*96];
__device__ unsigned W2P[96*96];

__device__ __forceinline__ float geluf(float v) {
    return 0.5f * v * (1.0f + erff(v * 0.70710678118654752f));
}
// fast tanh: 1 - 2/(e^{2x}+1); saturates correctly at +-inf, abs err ~1e-5
__device__ __forceinline__ float ftanh(float x) {
    float e = __expf(2.0f * x);
    return 1.0f - __fdividef(2.0f, e + 1.0f);
}
__device__ __forceinline__ unsigned f2tf32(float f) {
    unsigned r;
    asm("cvt.rna.tf32.f32 %0, %1;" : "=r"(r) : "f"(f));
    return r;
}
__device__ __forceinline__ int kperm16(int k) {
    int g = k & ~15, j = k & 15;
    return g + ((j & 3) << 2) + (j >> 2);
}
__device__ __forceinline__ void mma_tf32(float* c, const unsigned* a, const unsigned* b) {
    asm volatile(
        "mma.sync.aligned.m16n8k8.row.col.f32.tf32.tf32.f32 "
        "{%0,%1,%2,%3}, {%4,%5,%6,%7}, {%8,%9}, {%0,%1,%2,%3};"
        : "+f"(c[0]), "+f"(c[1]), "+f"(c[2]), "+f"(c[3])
        : "r"(a[0]), "r"(a[1]), "r"(a[2]), "r"(a[3]), "r"(b[0]), "r"(b[1]));
}
__device__ __forceinline__ void stage4(unsigned* row, int sw, int c, float x, float y, float z, float w) {
    int g = (c >> 2) << 4, r = c & 3;
    row[(g + r     ) ^ sw] = f2tf32(x);
    row[(g + r + 4 ) ^ sw] = f2tf32(y);
    row[(g + r + 8 ) ^ sw] = f2tf32(z);
    row[(g + r + 12) ^ sw] = f2tf32(w);
}

// ================= prep: weights + gather offsets =================
__global__ void kprep(const float* __restrict__ inproj, const float* __restrict__ Wo,
                      const float* __restrict__ W1, const float* __restrict__ W2,
                      const int* __restrict__ curves)
{
    int i = blockIdx.x * 256 + threadIdx.x;
    if (i < 320*128) {
        int n = i >> 7, k = i & 127;
        float v = (n < DPROJ) ? inproj[(size_t)k*DPROJ + n] : 0.0f;
        Wp1[n*128 + kperm16(k)] = f2tf32(v);
    }
    if (i < 96*128) {
        int n = i >> 7, k = i & 127;
        WoP[n*128 + kperm16(k)] = f2tf32(Wo[(size_t)k*96 + n]);
    }
    if (i < 96*96) {
        int n = i / 96, k = i - n*96;
        W1P[n*96 + kperm16(k)] = f2tf32(W1[(size_t)k*96 + n]);
        W2P[n*96 + kperm16(k)] = f2tf32(W2[(size_t)k*96 + n]);
    }
    if (i < NTOK) {
        int b  = i / (TT*PP);
        int tp = i - b*TT*PP;
        int t  = tp / PP;
        int p  = tp - t*PP;
        Goff[i] = (b*TT + t)*PP + curves[b*PP + p];
    }
}

// ================= khr: Hr = ftanh(xhres @ embed_w + embed_b) for ALL source tokens =====
// 8 threads per token (4 outputs each); grid NTOK*8/256 = 7680
__global__ void khr(const float* __restrict__ xhres,
                    const float* __restrict__ embed_w,
                    const float* __restrict__ embed_b)
{
    int i = blockIdx.x * 256 + threadIdx.x;
    int tok = i >> 3;
    int j0  = (i & 7) * 4;
    const float* xh = xhres + (size_t)tok*28;
    float a0 = embed_b[j0], a1 = embed_b[j0+1], a2 = embed_b[j0+2], a3 = embed_b[j0+3];
    #pragma unroll
    for (int k = 0; k < 28; k++) {
        float hk = xh[k];
        a0 = fmaf(hk, embed_w[k*32 + j0    ], a0);
        a1 = fmaf(hk, embed_w[k*32 + j0 + 1], a1);
        a2 = fmaf(hk, embed_w[k*32 + j0 + 2], a2);
        a3 = fmaf(hk, embed_w[k*32 + j0 + 3], a3);
    }
    *(float4*)(Hr + (size_t)tok*32 + j0) =
        make_float4(ftanh(a0), ftanh(a1), ftanh(a2), ftanh(a3));
}

// ================= K012: prologue + in_proj GEMM + mamba =================
// R13 + Hr-precomputed embed + __logf softplus.
// CTA = (b, tg, qgrp): 60 tokens; 256 threads; 2 CTAs/SM; grid 4096.
__global__ void __launch_bounds__(256, 2) k012_fused(
    const float* __restrict__ x,
    const float* __restrict__ xstat,
    const float* __restrict__ loan1_w,
    const float* __restrict__ loan1_b,
    const float* __restrict__ cw_f, const float* __restrict__ cb_f,
    const float* __restrict__ dtb_f, const float* __restrict__ al_f,
    const float* __restrict__ Dp_f, const float* __restrict__ nw_f,
    const float* __restrict__ cw_b, const float* __restrict__ cb_b,
    const float* __restrict__ dtb_b, const float* __restrict__ al_b,
    const float* __restrict__ Dp_b, const float* __restrict__ nw_b)
{
    extern __shared__ float smx[];
    float*    u_s = smx;                     // [64][268] fp32
    float*    ovl = smx + 64*268;            // overlay: As (GEMM) then xc0/xc1
    unsigned* As  = (unsigned*)ovl;          // [64][128] swizzled tf32
    float*    dtA = smx + 64*268 + 64*128;   // dt[2][240] dA[2][240]
    __shared__ float Aneg[2][8];

    const int blk  = blockIdx.x;
    const int b    = blk >> 11;
    const int tg   = (blk >> 10) & 1;
    const int qgrp = blk & 1023;
    const int tid  = threadIdx.x;
    const int warp = tid >> 5, lane = tid & 31;

    // ---- prologue: warp-per-token, 8 passes over 64 rows (60 real) ----
    for (int pass = 0; pass < 8; pass++) {
        const int m = pass*8 + warp;
        if (m < 60) {
            const int t_loc = m / 20;
            const int p_loc = m - t_loc*20;
            const int gi = (b*TT + tg*3 + t_loc)*PP + qgrp*20 + p_loc;
            const size_t base = (size_t)Goff[gi];

            float sval = (lane < 8) ? xstat[base*8 + lane] : 0.0f;

            float v0, v1, v2, v3;
            if (lane < 24) {
                float4 xv = *(const float4*)(x + base*96 + lane*4);
                v0 = xv.x; v1 = xv.y; v2 = xv.z; v3 = xv.w;
            } else {
                float4 hv = *(const float4*)(Hr + base*32 + (lane - 24)*4);
                v0 = hv.x; v1 = hv.y; v2 = hv.z; v3 = hv.w;
            }
            float s1 = v0+v1+v2+v3;
            float s2 = v0*v0+v1*v1+v2*v2+v3*v3;
            #pragma unroll
            for (int o = 16; o > 0; o >>= 1) {
                s1 += __shfl_xor_sync(0xffffffffu, s1, o);
                s2 += __shfl_xor_sync(0xffffffffu, s2, o);
            }
            float mu  = s1 * (1.0f/128.0f);
            float var = s2 * (1.0f/128.0f) - mu*mu;
            float rs  = rsqrtf(var + 1e-5f);
            float sv[8];
            #pragma unroll
            for (int k = 0; k < 8; k++) sv[k] = __shfl_sync(0xffffffffu, sval, k);
            const int c = lane*4;
            float o0 = loan1_b[c], o1 = loan1_b[c+1], o2 = loan1_b[c+2], o3 = loan1_b[c+3];
            #pragma unroll
            for (int k = 0; k < 8; k++) {
                o0 = fmaf(sv[k], loan1_w[k*128 + c    ], o0);
                o1 = fmaf(sv[k], loan1_w[k*128 + c + 1], o1);
                o2 = fmaf(sv[k], loan1_w[k*128 + c + 2], o2);
                o3 = fmaf(sv[k], loan1_w[k*128 + c + 3], o3);
            }
            o0 = (v0 - mu)*rs + ftanh(o0);
            o1 = (v1 - mu)*rs + ftanh(o1);
            o2 = (v2 - mu)*rs + ftanh(o2);
            o3 = (v3 - mu)*rs + ftanh(o3);
            stage4(As + m*128, (m&1)<<4, lane, o0, o1, o2, o3);
        } else {
            stage4(As + m*128, (m&1)<<4, lane, 0.f, 0.f, 0.f, 0.f);
        }
    }
    __syncthreads();

    // ---- GEMM: u = xn @ Wp1, M=64, K=128, into u_s (N=288 trim) ----
    {
        const int gid = lane >> 2, tq = lane & 3;
        const int wm = warp & 1, wn = warp >> 1;

        // chunk0: cols 0..159
        {
            float acc[2][5][4] = {};
            #pragma unroll
            for (int it = 0; it < 8; it++) {
                const int cb = it*16 + tq*4;
                uint4 a0v[2], a8v[2], bv[5];
                #pragma unroll
                for (int mt = 0; mt < 2; mt++) {
                    int r0 = wm*32 + mt*16 + gid;
                    int sw = (r0 & 1) << 4;
                    a0v[mt] = *(const uint4*)(As + r0*128 + (cb ^ sw));
                    a8v[mt] = *(const uint4*)(As + (r0+8)*128 + (cb ^ sw));
                }
                #pragma unroll
                for (int nt = 0; nt < 5; nt++) {
                    int nr = wn*40 + nt*8 + gid;
                    bv[nt] = *(const uint4*)(Wp1 + nr*128 + cb);
                }
                #pragma unroll
                for (int mt = 0; mt < 2; mt++) {
                    #pragma unroll
                    for (int nt = 0; nt < 5; nt++) {
                        unsigned aa1[4] = {a0v[mt].x, a8v[mt].x, a0v[mt].y, a8v[mt].y};
                        unsigned bb1[2] = {bv[nt].x, bv[nt].y};
                        mma_tf32(acc[mt][nt], aa1, bb1);
                        unsigned aa2[4] = {a0v[mt].z, a8v[mt].z, a0v[mt].w, a8v[mt].w};
                        unsigned bb2[2] = {bv[nt].z, bv[nt].w};
                        mma_tf32(acc[mt][nt], aa2, bb2);
                    }
                }
            }
            #pragma unroll
            for (int mt = 0; mt < 2; mt++) {
                int row = wm*32 + mt*16 + gid;
                #pragma unroll
                for (int nt = 0; nt < 5; nt++) {
                    int col = wn*40 + nt*8 + tq*2;
                    *(float2*)(u_s + row*268 + col) =
                        make_float2(acc[mt][nt][0], acc[mt][nt][1]);
                    *(float2*)(u_s + (row+8)*268 + col) =
                        make_float2(acc[mt][nt][2], acc[mt][nt][3]);
                }
            }
        }
        // chunk1: cols 160..287 (only 160..265 stored)
        {
            float acc[2][4][4] = {};
            #pragma unroll
            for (int it = 0; it < 8; it++) {
                const int cb = it*16 + tq*4;
                uint4 a0v[2], a8v[2], bv[4];
                #pragma unroll
                for (int mt = 0; mt < 2; mt++) {
                    int r0 = wm*32 + mt*16 + gid;
                    int sw = (r0 & 1) << 4;
                    a0v[mt] = *(const uint4*)(As + r0*128 + (cb ^ sw));
                    a8v[mt] = *(const uint4*)(As + (r0+8)*128 + (cb ^ sw));
                }
                #pragma unroll
                for (int nt = 0; nt < 4; nt++) {
                    int nr = 160 + wn*32 + nt*8 + gid;
                    bv[nt] = *(const uint4*)(Wp1 + nr*128 + cb);
                }
                #pragma unroll
                for (int mt = 0; mt < 2; mt++) {
                    #pragma unroll
                    for (int nt = 0; nt < 4; nt++) {
                        unsigned aa1[4] = {a0v[mt].x, a8v[mt].x, a0v[mt].y, a8v[mt].y};
                        unsigned bb1[2] = {bv[nt].x, bv[nt].y};
                        mma_tf32(acc[mt][nt], aa1, bb1);
                        unsigned aa2[4] = {a0v[mt].z, a8v[mt].z, a0v[mt].w, a8v[mt].w};
                        unsigned bb2[2] = {bv[nt].z, bv[nt].w};
                        mma_tf32(acc[mt][nt], aa2, bb2);
                    }
                }
            }
            #pragma unroll
            for (int mt = 0; mt < 2; mt++) {
                int row = wm*32 + mt*16 + gid;
                #pragma unroll
                for (int nt = 0; nt < 4; nt++) {
                    int col = 160 + wn*32 + nt*8 + tq*2;
                    if (col < DPROJ) {
                        *(float2*)(u_s + row*268 + col) =
                            make_float2(acc[mt][nt][0], acc[mt][nt][1]);
                        *(float2*)(u_s + (row+8)*268 + col) =
                            make_float2(acc[mt][nt][2], acc[mt][nt][3]);
                    }
                }
            }
        }
    }
    if (tid < 16) Aneg[tid>>3][tid&7] = -__expf((tid < 8 ? al_f : al_b)[tid & 7]);
    __syncthreads();   // u_s complete; As region free -> xc overlay

    // ---- mamba: 2 rounds (fwd, bwd); group g = seq (qg = qgrp*2+g) ----
    const int g  = tid >> 7;
    const int lt = tid & 127;
    float* xcg = ovl + g*3960;           // [30][132]
    float* dts = dtA + g*240;
    float* dAs = dtA + 480 + g*240;
    const int qg_src = qgrp*2 + g;

    #pragma unroll
    for (int r = 0; r < 2; r++) {
        const float* conv_w = r ? cw_b  : cw_f;
        const float* conv_b = r ? cb_b  : cb_f;
        const float* dtbp   = r ? dtb_b : dtb_f;
        const float* Dpp    = r ? Dp_b  : Dp_f;

        // dt = softplus(raw+bias), dA = exp(dt*A)  (fast-math exp/log)
        for (int i = lt; i < 240; i += 128) {
            int l = i >> 3, h = i & 7;
            int l10 = l / 10, lr = l - l10*10;
            int lu_r = r ? (9 - lr) : lr;
            int mu_ = l10*20 + g*10 + lu_r;
            float raw = u_s[mu_*268 + 258 + h] + dtbp[h];
            float dt = (raw > 20.f) ? raw : __logf(1.0f + __expf(raw));
            dts[l*8 + h] = dt;
            dAs[l*8 + h] = __expf(dt * Aneg[r][h]);
        }
        // causal depthwise conv + silu: ONE pass; threads 0,1 also do B/C channels
        {
            const int c = lt;
            float w0 = conv_w[c*3+0], w1 = conv_w[c*3+1], w2 = conv_w[c*3+2];
            float bias = conv_b[c];
            float p2 = 0.f, p1 = 0.f;
            const bool dual = (lt < 2);
            const int c2 = 128 + lt;
            float w0b = 0.f, w1b = 0.f, w2b = 0.f, biasb = 0.f;
            float q2 = 0.f, q1 = 0.f;
            if (dual) {
                w0b = conv_w[c2*3+0]; w1b = conv_w[c2*3+1]; w2b = conv_w[c2*3+2];
                biasb = conv_b[c2];
            }
            #pragma unroll
            for (int l = 0; l < 30; l++) {
                int l10 = l / 10, lr = l - l10*10;
                int mu_ = l10*20 + g*10 + (r ? (9 - lr) : lr);
                float v = u_s[mu_*268 + 128 + c];
                float a = fmaf(p2, w0, fmaf(p1, w1, fmaf(v, w2, bias)));
                xcg[l*132 + c] = __fdividef(a, 1.f + __expf(-a));
                p2 = p1; p1 = v;
                if (dual) {
                    float vb = u_s[mu_*268 + 128 + c2];
                    float ab = fmaf(q2, w0b, fmaf(q1, w1b, fmaf(vb, w2b, biasb)));
                    xcg[l*132 + c2] = __fdividef(ab, 1.f + __expf(-ab));
                    q2 = q1; q1 = vb;
                }
            }
        }
        __syncthreads();

        // scalar scan; y overlays xc column c (fast-math silu gate)
        {
            const int c = lt, h = c >> 4;
            const float Dh = Dpp[h];
            float hs = 0.f;
            #pragma unroll
            for (int l = 0; l < 30; l++) {
                int l10 = l / 10, lr = l - l10*10;
                int mu_ = l10*20 + g*10 + (r ? (9 - lr) : lr);
                float xv = xcg[l*132 + c];
                float Bv = xcg[l*132 + 128];
                float Cv = xcg[l*132 + 129];
                hs = fmaf(hs, dAs[l*8+h], dts[l*8+h]*xv*Bv);
                float y = fmaf(hs, Cv, xv*Dh);
                float z = u_s[mu_*268 + c];
                y *= __fdividef(z, 1.f + __expf(-z));
                xcg[l*132 + c] = y;
            }
        }
        __syncthreads();

        // RMS + scatter
        {
            const int w4 = warp & 3;
            const float* nww = r ? nw_b : nw_f;
            float* ybuf = r ? S_yb : S_yf;
            const int qgu = r ? (2047 - qg_src) : qg_src;
            const int abase = (tg*1024 + (qgu>>1))*6 + (qgu&1);
            for (int l = w4; l < 30; l += 4) {
                float4 v = *(float4*)(xcg + l*132 + lane*4);
                float ss = v.x*v.x + v.y*v.y + v.z*v.z + v.w*v.w;
                #pragma unroll
                for (int o = 16; o > 0; o >>= 1) ss += __shfl_xor_sync(0xffffffffu, ss, o);
                float scale = rsqrtf(ss*(1.f/128.f) + 1e-5f) * 0.5f;
                int l3 = l / 3;
                int f = l3*12288 + abase + (l - l3*3)*2;
                int t_out = f / PP;
                int p_out = f - t_out*PP;
                if (r) p_out = PP-1 - p_out;
                float4 w = *(const float4*)(nww + lane*4);
                float4 o;
                o.x = v.x*scale*w.x; o.y = v.y*scale*w.y;
                o.z = v.z*scale*w.z; o.w = v.w*scale*w.w;
                *(float4*)(ybuf + ((size_t)(b*TT + t_out)*PP + p_out)*128 + lane*4) = o;
            }
        }
        __syncthreads();
    }
}

// ===== GEMM helper: M64xN96, A in smem, B via LDG =====
template<int KIT, int KSTRIDE>
__device__ __forceinline__ void gemm_ldgB(const unsigned* __restrict__ Ab, int SA,
                                          const unsigned* __restrict__ Wg,
                                          int wm, int wn, int gid, int tq,
                                          float (&acc)[2][3][4])
{
    #pragma unroll
    for (int it = 0; it < KIT; it++) {
        const int cb = it*16 + tq*4;
        uint4 a0v[2], a8v[2], bv[3];
        #pragma unroll
        for (int mt = 0; mt < 2; mt++) {
            int r0 = wm*32 + mt*16 + gid;
            int sw = (r0 & 1) << 4;
            a0v[mt] = *(const uint4*)(Ab + r0*SA + (cb ^ sw));
            a8v[mt] = *(const uint4*)(Ab + (r0+8)*SA + (cb ^ sw));
        }
        #pragma unroll
        for (int nt = 0; nt < 3; nt++) {
            int nr = wn*24 + nt*8 + gid;
            bv[nt] = *(const uint4*)(Wg + nr*KSTRIDE + cb);
        }
        #pragma unroll
        for (int mt = 0; mt < 2; mt++) {
            #pragma unroll
            for (int nt = 0; nt < 3; nt++) {
                unsigned aa1[4] = {a0v[mt].x, a8v[mt].x, a0v[mt].y, a8v[mt].y};
                unsigned bb1[2] = {bv[nt].x, bv[nt].y};
                mma_tf32(acc[mt][nt], aa1, bb1);
                unsigned aa2[4] = {a0v[mt].z, a8v[mt].z, a0v[mt].w, a8v[mt].w};
                unsigned bb2[2] = {bv[nt].z, bv[nt].w};
                mma_tf32(acc[mt][nt], aa2, bb2);
            }
        }
    }
}

// ================= K34: out_proj + residual + LN + loan2 + MLP, fused ==========
__global__ void __launch_bounds__(256, 3) k34_fused(
    const float* __restrict__ x,
    const float* __restrict__ xstat,
    const float* __restrict__ loan2_w,
    const float* __restrict__ loan2_b,
    const float* __restrict__ b1,
    const float* __restrict__ b2,
    float* __restrict__ out)
{
    extern __shared__ unsigned smf[];
    unsigned* As  = smf;                     // [64][128]; tts/hs overlay
    float*    x1s = (float*)(smf + 64*128);  // [64][100]
    unsigned* tts = As;
    unsigned* hs  = As;

    const int tid = threadIdx.x;
    const int m_base = blockIdx.x * 64;
    const int warp = tid >> 5, lane = tid & 31;
    const int gid = lane >> 2, tq = lane & 3;
    const int wm = warp & 1, wn = warp >> 1;

    for (int i = tid; i < 64*32; i += 256) {
        int m = i >> 5, c = i & 31;
        size_t off = (size_t)(m_base+m)*128 + c*4;
        float4 a = *(const float4*)(S_yf + off);
        float4 q = *(const float4*)(S_yb + off);
        stage4(As + m*128, (m&1)<<4, c, a.x+q.x, a.y+q.y, a.z+q.z, a.w+q.w);
    }
    __syncthreads();

    float acc[2][3][4] = {};
    gemm_ldgB<8,128>(As, 128, WoP, wm, wn, gid, tq, acc);

    #pragma unroll
    for (int mt = 0; mt < 2; mt++) {
        int r = wm*32 + mt*16 + gid;
        #pragma unroll
        for (int nt = 0; nt < 3; nt++) {
            int c = wn*24 + nt*8 + tq*2;
            x1s[r*100 + c]     = acc[mt][nt][0];
            x1s[r*100 + c + 1] = acc[mt][nt][1];
            x1s[(r+8)*100 + c]     = acc[mt][nt][2];
            x1s[(r+8)*100 + c + 1] = acc[mt][nt][3];
        }
    }
    __syncthreads();

    for (int r = warp; r < 64; r += 8) {
        int gm = m_base + r;
        size_t base = (size_t)Goff[gm];
        size_t xb = base*96;
        float v0 = x1s[r*100 + lane*3 + 0] + x[xb + lane*3 + 0];
        float v1 = x1s[r*100 + lane*3 + 1] + x[xb + lane*3 + 1];
        float v2 = x1s[r*100 + lane*3 + 2] + x[xb + lane*3 + 2];
        x1s[r*100 + lane*3 + 0] = v0;
        x1s[r*100 + lane*3 + 1] = v1;
        x1s[r*100 + lane*3 + 2] = v2;
        float s1 = v0+v1+v2, s2 = v0*v0+v1*v1+v2*v2;
        #pragma unroll
        for (int o = 16; o > 0; o >>= 1) {
            s1 += __shfl_xor_sync(0xffffffffu, s1, o);
            s2 += __shfl_xor_sync(0xffffffffu, s2, o);
        }
        float mu  = s1 * (1.0f/96.0f);
        float var = s2 * (1.0f/96.0f) - mu*mu;
        float rs  = rsqrtf(var + 1e-5f);
        size_t sbase = base*8;
        float xs[8];
        #pragma unroll
        for (int k = 0; k < 8; k++) xs[k] = xstat[sbase + k];
        int swr = (r & 1) << 4;
        #pragma unroll
        for (int i2 = 0; i2 < 3; i2++) {
            int jj = lane*3 + i2;
            float a = loan2_b[jj];
            #pragma unroll
            for (int k = 0; k < 8; k++) a = fmaf(xs[k], loan2_w[k*96 + jj], a);
            float vv = (i2 == 0) ? v0 : ((i2 == 1) ? v1 : v2);
            tts[r*96 + (kperm16(jj) ^ swr)] = f2tf32((vv - mu)*rs + ftanh(a));
        }
    }
    __syncthreads();

    float acc1[2][3][4] = {};
    gemm_ldgB<6,96>(tts, 96, W1P, wm, wn, gid, tq, acc1);
    __syncthreads();

    #pragma unroll
    for (int mt = 0; mt < 2; mt++) {
        int r = wm*32 + mt*16 + gid;
        int swr = (r & 1) << 4;
        #pragma unroll
        for (int nt = 0; nt < 3; nt++) {
            int c = wn*24 + nt*8 + tq*2;
            float bb0 = b1[c], bb1 = b1[c+1];
            hs[r*96 + (kperm16(c)   ^ swr)] = f2tf32(geluf(acc1[mt][nt][0] + bb0));
            hs[r*96 + (kperm16(c+1) ^ swr)] = f2tf32(geluf(acc1[mt][nt][1] + bb1));
            hs[(r+8)*96 + (kperm16(c)   ^ swr)] = f2tf32(geluf(acc1[mt][nt][2] + bb0));
            hs[(r+8)*96 + (kperm16(c+1) ^ swr)] = f2tf32(geluf(acc1[mt][nt][3] + bb1));
        }
    }
    __syncthreads();

    float acc2[2][3][4] = {};
    gemm_ldgB<6,96>(hs, 96, W2P, wm, wn, gid, tq, acc2);

    #pragma unroll
    for (int mt = 0; mt < 2; mt++) {
        int r = wm*32 + mt*16 + gid;
        int gm0 = m_base + r, gm8 = gm0 + 8;
        #pragma unroll
        for (int nt = 0; nt < 3; nt++) {
            int c = wn*24 + nt*8 + tq*2;
            float bb0 = b2[c], bb1 = b2[c+1];
            *(float2*)(out + (size_t)gm0*96 + c) = make_float2(
                acc2[mt][nt][0] + bb0 + x1s[r*100 + c],
                acc2[mt][nt][1] + bb1 + x1s[r*100 + c + 1]);
            *(float2*)(out + (size_t)gm8*96 + c) = make_float2(
                acc2[mt][nt][2] + bb0 + x1s[(r+8)*100 + c],
                acc2[mt][nt][3] + bb1 + x1s[(r+8)*100 + c + 1]);
        }
    }
}

// ================= launcher =================
extern "C" void kernel_launch(void* const* d_in, const int* in_sizes, int n_in,
                              void* d_out, int out_size)
{
    const float* x       = (const float*)d_in[0];
    const float* xstat   = (const float*)d_in[1];
    const float* xhres   = (const float*)d_in[2];
    const int*   curves  = (const int*)  d_in[3];
    const float* embed_w = (const float*)d_in[4];
    const float* embed_b = (const float*)d_in[5];
    const float* loan1_w = (const float*)d_in[6];
    const float* loan1_b = (const float*)d_in[7];
    const float* loan2_w = (const float*)d_in[8];
    const float* loan2_b = (const float*)d_in[9];
    const float* in_proj = (const float*)d_in[10];
    const float* cw_f  = (const float*)d_in[11];
    const float* cb_f  = (const float*)d_in[12];
    const float* dtb_f = (const float*)d_in[13];
    const float* al_f  = (const float*)d_in[14];
    const float* Dp_f  = (const float*)d_in[15];
    const float* nw_f  = (const float*)d_in[16];
    const float* cw_b  = (const float*)d_in[17];
    const float* cb_b  = (const float*)d_in[18];
    const float* dtb_b = (const float*)d_in[19];
    const float* al_b  = (const float*)d_in[20];
    const float* Dp_b  = (const float*)d_in[21];
    const float* nw_b  = (const float*)d_in[22];
    const float* Wo    = (const float*)d_in[23];
    const float* W1    = (const float*)d_in[24];
    const float* b1    = (const float*)d_in[25];
    const float* W2    = (const float*)d_in[26];
    const float* b2    = (const float*)d_in[27];
    float* out = (float*)d_out;

    const int smem012 = (64*268 + 64*128 + 960) * 4;   // 105216
    const int smem34  = (64*128 + 64*100) * 4;         // 58368

    cudaFuncSetAttribute(k012_fused, cudaFuncAttributeMaxDynamicSharedMemorySize, smem012);
    cudaFuncSetAttribute(k34_fused,  cudaFuncAttributeMaxDynamicSharedMemorySize, smem34);

    kprep<<<NTOK/256, 256>>>(in_proj, Wo, W1, W2, curves);
    khr<<<NTOK*8/256, 256>>>(xhres, embed_w, embed_b);

    k012_fused<<<4096, 256, smem012>>>(x, xstat, loan1_w, loan1_b,
                                       cw_f, cb_f, dtb_f, al_f, Dp_f, nw_f,
                                       cw_b, cb_b, dtb_b, al_b, Dp_b, nw_b);

    k34_fused<<<NTOK/64, 256, smem34>>>(x, xstat, loan2_w, loan2_b, b1, b2, out);
}

// round 15
// speedup vs baseline: 1.5209x; 1.0045x over previous
#include <cuda_runtime.h>
#include <cuda_bf16.h>
#include <math.h>

#define BB 2
#define TT 6
#define PP 20480
#define NTOK (BB*TT*PP)      /* 245760 */
#define DPROJ 266

// ---------------- scratch ----------------
__device__ __nv_bfloat16 S_yf[(size_t)NTOK*128];   // 63 MB (was 126)
__device__ __nv_bfloat16 S_yb[(size_t)NTOK*128];
__device__ int   Goff[NTOK];
__device__ float Hr[(size_t)NTOK*32];   // precomputed tanh(xh@embed_w+b)
// pre-permuted tf32 weights (B operands, n-major, kperm16'd)
__device__ unsigned Wp1[320*128];
__device__ unsigned WoP[96*128];
__device__ unsigned W1P[96*96];
__device__ unsigned W2P[96*96];

__device__ __forceinline__ float geluf(float v) {
    return 0.5f * v * (1.0f + erff(v * 0.70710678118654752f));
}
// fast tanh: 1 - 2/(e^{2x}+1)
__device__ __forceinline__ float ftanh(float x) {
    float e = __expf(2.0f * x);
    return 1.0f - __fdividef(2.0f, e + 1.0f);
}
__device__ __forceinline__ unsigned f2tf32(float f) {
    unsigned r;
    asm("cvt.rna.tf32.f32 %0, %1;" : "=r"(r) : "f"(f));
    return r;
}
__device__ __forceinline__ int kperm16(int k) {
    int g = k & ~15, j = k & 15;
    return g + ((j & 3) << 2) + (j >> 2);
}
__device__ __forceinline__ void mma_tf32(float* c, const unsigned* a, const unsigned* b) {
    asm volatile(
        "mma.sync.aligned.m16n8k8.row.col.f32.tf32.tf32.f32 "
        "{%0,%1,%2,%3}, {%4,%5,%6,%7}, {%8,%9}, {%0,%1,%2,%3};"
        : "+f"(c[0]), "+f"(c[1]), "+f"(c[2]), "+f"(c[3])
        : "r"(a[0]), "r"(a[1]), "r"(a[2]), "r"(a[3]), "r"(b[0]), "r"(b[1]));
}
__device__ __forceinline__ void stage4(unsigned* row, int sw, int c, float x, float y, float z, float w) {
    int g = (c >> 2) << 4, r = c & 3;
    row[(g + r     ) ^ sw] = f2tf32(x);
    row[(g + r + 4 ) ^ sw] = f2tf32(y);
    row[(g + r + 8 ) ^ sw] = f2tf32(z);
    row[(g + r + 12) ^ sw] = f2tf32(w);
}

// ================= prep: weights + gather offsets =================
__global__ void kprep(const float* __restrict__ inproj, const float* __restrict__ Wo,
                      const float* __restrict__ W1, const float* __restrict__ W2,
                      const int* __restrict__ curves)
{
    int i = blockIdx.x * 256 + threadIdx.x;
    if (i < 320*128) {
        int n = i >> 7, k = i & 127;
        float v = (n < DPROJ) ? inproj[(size_t)k*DPROJ + n] : 0.0f;
        Wp1[n*128 + kperm16(k)] = f2tf32(v);
    }
    if (i < 96*128) {
        int n = i >> 7, k = i & 127;
        WoP[n*128 + kperm16(k)] = f2tf32(Wo[(size_t)k*96 + n]);
    }
    if (i < 96*96) {
        int n = i / 96, k = i - n*96;
        W1P[n*96 + kperm16(k)] = f2tf32(W1[(size_t)k*96 + n]);
        W2P[n*96 + kperm16(k)] = f2tf32(W2[(size_t)k*96 + n]);
    }
    if (i < NTOK) {
        int b  = i / (TT*PP);
        int tp = i - b*TT*PP;
        int t  = tp / PP;
        int p  = tp - t*PP;
        Goff[i] = (b*TT + t)*PP + curves[b*PP + p];
    }
}

// ================= khr: Hr = ftanh(xhres @ embed_w + embed_b) =================
__global__ void khr(const float* __restrict__ xhres,
                    const float* __restrict__ embed_w,
                    const float* __restrict__ embed_b)
{
    int i = blockIdx.x * 256 + threadIdx.x;
    int tok = i >> 3;
    int j0  = (i & 7) * 4;
    const float* xh = xhres + (size_t)tok*28;
    float a0 = embed_b[j0], a1 = embed_b[j0+1], a2 = embed_b[j0+2], a3 = embed_b[j0+3];
    #pragma unroll
    for (int k = 0; k < 28; k++) {
        float hk = xh[k];
        a0 = fmaf(hk, embed_w[k*32 + j0    ], a0);
        a1 = fmaf(hk, embed_w[k*32 + j0 + 1], a1);
        a2 = fmaf(hk, embed_w[k*32 + j0 + 2], a2);
        a3 = fmaf(hk, embed_w[k*32 + j0 + 3], a3);
    }
    *(float4*)(Hr + (size_t)tok*32 + j0) =
        make_float4(ftanh(a0), ftanh(a1), ftanh(a2), ftanh(a3));
}

// ================= K012: prologue + in_proj GEMM + mamba =================
// R14 + bf16 y output.
__global__ void __launch_bounds__(256, 2) k012_fused(
    const float* __restrict__ x,
    const float* __restrict__ xstat,
    const float* __restrict__ loan1_w,
    const float* __restrict__ loan1_b,
    const float* __restrict__ cw_f, const float* __restrict__ cb_f,
    const float* __restrict__ dtb_f, const float* __restrict__ al_f,
    const float* __restrict__ Dp_f, const float* __restrict__ nw_f,
    const float* __restrict__ cw_b, const float* __restrict__ cb_b,
    const float* __restrict__ dtb_b, const float* __restrict__ al_b,
    const float* __restrict__ Dp_b, const float* __restrict__ nw_b)
{
    extern __shared__ float smx[];
    float*    u_s = smx;                     // [64][268] fp32
    float*    ovl = smx + 64*268;            // overlay: As (GEMM) then xc0/xc1
    unsigned* As  = (unsigned*)ovl;          // [64][128] swizzled tf32
    float*    dtA = smx + 64*268 + 64*128;   // dt[2][240] dA[2][240]
    __shared__ float Aneg[2][8];

    const int blk  = blockIdx.x;
    const int b    = blk >> 11;
    const int tg   = (blk >> 10) & 1;
    const int qgrp = blk & 1023;
    const int tid  = threadIdx.x;
    const int warp = tid >> 5, lane = tid & 31;

    // ---- prologue: warp-per-token, 8 passes over 64 rows (60 real) ----
    for (int pass = 0; pass < 8; pass++) {
        const int m = pass*8 + warp;
        if (m < 60) {
            const int t_loc = m / 20;
            const int p_loc = m - t_loc*20;
            const int gi = (b*TT + tg*3 + t_loc)*PP + qgrp*20 + p_loc;
            const size_t base = (size_t)Goff[gi];

            float sval = (lane < 8) ? xstat[base*8 + lane] : 0.0f;

            float v0, v1, v2, v3;
            if (lane < 24) {
                float4 xv = *(const float4*)(x + base*96 + lane*4);
                v0 = xv.x; v1 = xv.y; v2 = xv.z; v3 = xv.w;
            } else {
                float4 hv = *(const float4*)(Hr + base*32 + (lane - 24)*4);
                v0 = hv.x; v1 = hv.y; v2 = hv.z; v3 = hv.w;
            }
            float s1 = v0+v1+v2+v3;
            float s2 = v0*v0+v1*v1+v2*v2+v3*v3;
            #pragma unroll
            for (int o = 16; o > 0; o >>= 1) {
                s1 += __shfl_xor_sync(0xffffffffu, s1, o);
                s2 += __shfl_xor_sync(0xffffffffu, s2, o);
            }
            float mu  = s1 * (1.0f/128.0f);
            float var = s2 * (1.0f/128.0f) - mu*mu;
            float rs  = rsqrtf(var + 1e-5f);
            float sv[8];
            #pragma unroll
            for (int k = 0; k < 8; k++) sv[k] = __shfl_sync(0xffffffffu, sval, k);
            const int c = lane*4;
            float o0 = loan1_b[c], o1 = loan1_b[c+1], o2 = loan1_b[c+2], o3 = loan1_b[c+3];
            #pragma unroll
            for (int k = 0; k < 8; k++) {
                o0 = fmaf(sv[k], loan1_w[k*128 + c    ], o0);
                o1 = fmaf(sv[k], loan1_w[k*128 + c + 1], o1);
                o2 = fmaf(sv[k], loan1_w[k*128 + c + 2], o2);
                o3 = fmaf(sv[k], loan1_w[k*128 + c + 3], o3);
            }
            o0 = (v0 - mu)*rs + ftanh(o0);
            o1 = (v1 - mu)*rs + ftanh(o1);
            o2 = (v2 - mu)*rs + ftanh(o2);
            o3 = (v3 - mu)*rs + ftanh(o3);
            stage4(As + m*128, (m&1)<<4, lane, o0, o1, o2, o3);
        } else {
            stage4(As + m*128, (m&1)<<4, lane, 0.f, 0.f, 0.f, 0.f);
        }
    }
    __syncthreads();

    // ---- GEMM: u = xn @ Wp1, M=64, K=128, into u_s (N=288 trim) ----
    {
        const int gid = lane >> 2, tq = lane & 3;
        const int wm = warp & 1, wn = warp >> 1;

        // chunk0: cols 0..159
        {
            float acc[2][5][4] = {};
            #pragma unroll
            for (int it = 0; it < 8; it++) {
                const int cb = it*16 + tq*4;
                uint4 a0v[2], a8v[2], bv[5];
                #pragma unroll
                for (int mt = 0; mt < 2; mt++) {
                    int r0 = wm*32 + mt*16 + gid;
                    int sw = (r0 & 1) << 4;
                    a0v[mt] = *(const uint4*)(As + r0*128 + (cb ^ sw));
                    a8v[mt] = *(const uint4*)(As + (r0+8)*128 + (cb ^ sw));
                }
                #pragma unroll
                for (int nt = 0; nt < 5; nt++) {
                    int nr = wn*40 + nt*8 + gid;
                    bv[nt] = *(const uint4*)(Wp1 + nr*128 + cb);
                }
                #pragma unroll
                for (int mt = 0; mt < 2; mt++) {
                    #pragma unroll
                    for (int nt = 0; nt < 5; nt++) {
                        unsigned aa1[4] = {a0v[mt].x, a8v[mt].x, a0v[mt].y, a8v[mt].y};
                        unsigned bb1[2] = {bv[nt].x, bv[nt].y};
                        mma_tf32(acc[mt][nt], aa1, bb1);
                        unsigned aa2[4] = {a0v[mt].z, a8v[mt].z, a0v[mt].w, a8v[mt].w};
                        unsigned bb2[2] = {bv[nt].z, bv[nt].w};
                        mma_tf32(acc[mt][nt], aa2, bb2);
                    }
                }
            }
            #pragma unroll
            for (int mt = 0; mt < 2; mt++) {
                int row = wm*32 + mt*16 + gid;
                #pragma unroll
                for (int nt = 0; nt < 5; nt++) {
                    int col = wn*40 + nt*8 + tq*2;
                    *(float2*)(u_s + row*268 + col) =
                        make_float2(acc[mt][nt][0], acc[mt][nt][1]);
                    *(float2*)(u_s + (row+8)*268 + col) =
                        make_float2(acc[mt][nt][2], acc[mt][nt][3]);
                }
            }
        }
        // chunk1: cols 160..287 (only 160..265 stored)
        {
            float acc[2][4][4] = {};
            #pragma unroll
            for (int it = 0; it < 8; it++) {
                const int cb = it*16 + tq*4;
                uint4 a0v[2], a8v[2], bv[4];
                #pragma unroll
                for (int mt = 0; mt < 2; mt++) {
                    int r0 = wm*32 + mt*16 + gid;
                    int sw = (r0 & 1) << 4;
                    a0v[mt] = *(const uint4*)(As + r0*128 + (cb ^ sw));
                    a8v[mt] = *(const uint4*)(As + (r0+8)*128 + (cb ^ sw));
                }
                #pragma unroll
                for (int nt = 0; nt < 4; nt++) {
                    int nr = 160 + wn*32 + nt*8 + gid;
                    bv[nt] = *(const uint4*)(Wp1 + nr*128 + cb);
                }
                #pragma unroll
                for (int mt = 0; mt < 2; mt++) {
                    #pragma unroll
                    for (int nt = 0; nt < 4; nt++) {
                        unsigned aa1[4] = {a0v[mt].x, a8v[mt].x, a0v[mt].y, a8v[mt].y};
                        unsigned bb1[2] = {bv[nt].x, bv[nt].y};
                        mma_tf32(acc[mt][nt], aa1, bb1);
                        unsigned aa2[4] = {a0v[mt].z, a8v[mt].z, a0v[mt].w, a8v[mt].w};
                        unsigned bb2[2] = {bv[nt].z, bv[nt].w};
                        mma_tf32(acc[mt][nt], aa2, bb2);
                    }
                }
            }
            #pragma unroll
            for (int mt = 0; mt < 2; mt++) {
                int row = wm*32 + mt*16 + gid;
                #pragma unroll
                for (int nt = 0; nt < 4; nt++) {
                    int col = 160 + wn*32 + nt*8 + tq*2;
                    if (col < DPROJ) {
                        *(float2*)(u_s + row*268 + col) =
                            make_float2(acc[mt][nt][0], acc[mt][nt][1]);
                        *(float2*)(u_s + (row+8)*268 + col) =
                            make_float2(acc[mt][nt][2], acc[mt][nt][3]);
                    }
                }
            }
        }
    }
    if (tid < 16) Aneg[tid>>3][tid&7] = -__expf((tid < 8 ? al_f : al_b)[tid & 7]);
    __syncthreads();   // u_s complete; As region free -> xc overlay

    // ---- mamba: 2 rounds (fwd, bwd); group g = seq (qg = qgrp*2+g) ----
    const int g  = tid >> 7;
    const int lt = tid & 127;
    float* xcg = ovl + g*3960;           // [30][132]
    float* dts = dtA + g*240;
    float* dAs = dtA + 480 + g*240;
    const int qg_src = qgrp*2 + g;

    #pragma unroll
    for (int r = 0; r < 2; r++) {
        const float* conv_w = r ? cw_b  : cw_f;
        const float* conv_b = r ? cb_b  : cb_f;
        const float* dtbp   = r ? dtb_b : dtb_f;
        const float* Dpp    = r ? Dp_b  : Dp_f;

        for (int i = lt; i < 240; i += 128) {
            int l = i >> 3, h = i & 7;
            int l10 = l / 10, lr = l - l10*10;
            int lu_r = r ? (9 - lr) : lr;
            int mu_ = l10*20 + g*10 + lu_r;
            float raw = u_s[mu_*268 + 258 + h] + dtbp[h];
            float dt = (raw > 20.f) ? raw : __logf(1.0f + __expf(raw));
            dts[l*8 + h] = dt;
            dAs[l*8 + h] = __expf(dt * Aneg[r][h]);
        }
        {
            const int c = lt;
            float w0 = conv_w[c*3+0], w1 = conv_w[c*3+1], w2 = conv_w[c*3+2];
            float bias = conv_b[c];
            float p2 = 0.f, p1 = 0.f;
            const bool dual = (lt < 2);
            const int c2 = 128 + lt;
            float w0b = 0.f, w1b = 0.f, w2b = 0.f, biasb = 0.f;
            float q2 = 0.f, q1 = 0.f;
            if (dual) {
                w0b = conv_w[c2*3+0]; w1b = conv_w[c2*3+1]; w2b = conv_w[c2*3+2];
                biasb = conv_b[c2];
            }
            #pragma unroll
            for (int l = 0; l < 30; l++) {
                int l10 = l / 10, lr = l - l10*10;
                int mu_ = l10*20 + g*10 + (r ? (9 - lr) : lr);
                float v = u_s[mu_*268 + 128 + c];
                float a = fmaf(p2, w0, fmaf(p1, w1, fmaf(v, w2, bias)));
                xcg[l*132 + c] = __fdividef(a, 1.f + __expf(-a));
                p2 = p1; p1 = v;
                if (dual) {
                    float vb = u_s[mu_*268 + 128 + c2];
                    float ab = fmaf(q2, w0b, fmaf(q1, w1b, fmaf(vb, w2b, biasb)));
                    xcg[l*132 + c2] = __fdividef(ab, 1.f + __expf(-ab));
                    q2 = q1; q1 = vb;
                }
            }
        }
        __syncthreads();

        {
            const int c = lt, h = c >> 4;
            const float Dh = Dpp[h];
            float hs = 0.f;
            #pragma unroll
            for (int l = 0; l < 30; l++) {
                int l10 = l / 10, lr = l - l10*10;
                int mu_ = l10*20 + g*10 + (r ? (9 - lr) : lr);
                float xv = xcg[l*132 + c];
                float Bv = xcg[l*132 + 128];
                float Cv = xcg[l*132 + 129];
                hs = fmaf(hs, dAs[l*8+h], dts[l*8+h]*xv*Bv);
                float y = fmaf(hs, Cv, xv*Dh);
                float z = u_s[mu_*268 + c];
                y *= __fdividef(z, 1.f + __expf(-z));
                xcg[l*132 + c] = y;
            }
        }
        __syncthreads();

        // RMS + scatter (bf16 output, 8B per thread per l)
        {
            const int w4 = warp & 3;
            const float* nww = r ? nw_b : nw_f;
            __nv_bfloat16* ybuf = r ? S_yb : S_yf;
            const int qgu = r ? (2047 - qg_src) : qg_src;
            const int abase = (tg*1024 + (qgu>>1))*6 + (qgu&1);
            for (int l = w4; l < 30; l += 4) {
                float4 v = *(float4*)(xcg + l*132 + lane*4);
                float ss = v.x*v.x + v.y*v.y + v.z*v.z + v.w*v.w;
                #pragma unroll
                for (int o = 16; o > 0; o >>= 1) ss += __shfl_xor_sync(0xffffffffu, ss, o);
                float scale = rsqrtf(ss*(1.f/128.f) + 1e-5f) * 0.5f;
                int l3 = l / 3;
                int f = l3*12288 + abase + (l - l3*3)*2;
                int t_out = f / PP;
                int p_out = f - t_out*PP;
                if (r) p_out = PP-1 - p_out;
                float4 w = *(const float4*)(nww + lane*4);
                __nv_bfloat162 pa = __floats2bfloat162_rn(v.x*scale*w.x, v.y*scale*w.y);
                __nv_bfloat162 pb = __floats2bfloat162_rn(v.z*scale*w.z, v.w*scale*w.w);
                uint2 pk = make_uint2(*(unsigned*)&pa, *(unsigned*)&pb);
                *(uint2*)(ybuf + ((size_t)(b*TT + t_out)*PP + p_out)*128 + lane*4) = pk;
            }
        }
        __syncthreads();
    }
}

// ===== GEMM helper: M64xN96, A in smem, B via LDG =====
template<int KIT, int KSTRIDE>
__device__ __forceinline__ void gemm_ldgB(const unsigned* __restrict__ Ab, int SA,
                                          const unsigned* __restrict__ Wg,
                                          int wm, int wn, int gid, int tq,
                                          float (&acc)[2][3][4])
{
    #pragma unroll
    for (int it = 0; it < KIT; it++) {
        const int cb = it*16 + tq*4;
        uint4 a0v[2], a8v[2], bv[3];
        #pragma unroll
        for (int mt = 0; mt < 2; mt++) {
            int r0 = wm*32 + mt*16 + gid;
            int sw = (r0 & 1) << 4;
            a0v[mt] = *(const uint4*)(Ab + r0*SA + (cb ^ sw));
            a8v[mt] = *(const uint4*)(Ab + (r0+8)*SA + (cb ^ sw));
        }
        #pragma unroll
        for (int nt = 0; nt < 3; nt++) {
            int nr = wn*24 + nt*8 + gid;
            bv[nt] = *(const uint4*)(Wg + nr*KSTRIDE + cb);
        }
        #pragma unroll
        for (int mt = 0; mt < 2; mt++) {
            #pragma unroll
            for (int nt = 0; nt < 3; nt++) {
                unsigned aa1[4] = {a0v[mt].x, a8v[mt].x, a0v[mt].y, a8v[mt].y};
                unsigned bb1[2] = {bv[nt].x, bv[nt].y};
                mma_tf32(acc[mt][nt], aa1, bb1);
                unsigned aa2[4] = {a0v[mt].z, a8v[mt].z, a0v[mt].w, a8v[mt].w};
                unsigned bb2[2] = {bv[nt].z, bv[nt].w};
                mma_tf32(acc[mt][nt], aa2, bb2);
            }
        }
    }
}

// ================= K34: out_proj + residual + LN + loan2 + MLP, fused ==========
__global__ void __launch_bounds__(256, 3) k34_fused(
    const float* __restrict__ x,
    const float* __restrict__ xstat,
    const float* __restrict__ loan2_w,
    const float* __restrict__ loan2_b,
    const float* __restrict__ b1,
    const float* __restrict__ b2,
    float* __restrict__ out)
{
    extern __shared__ unsigned smf[];
    unsigned* As  = smf;                     // [64][128]; tts/hs overlay
    float*    x1s = (float*)(smf + 64*128);  // [64][100]
    unsigned* tts = As;
    unsigned* hs  = As;

    const int tid = threadIdx.x;
    const int m_base = blockIdx.x * 64;
    const int warp = tid >> 5, lane = tid & 31;
    const int gid = lane >> 2, tq = lane & 3;
    const int wm = warp & 1, wn = warp >> 1;

    for (int i = tid; i < 64*32; i += 256) {
        int m = i >> 5, c = i & 31;
        size_t off = (size_t)(m_base+m)*128 + c*4;
        uint2 ua = *(const uint2*)(S_yf + off);
        uint2 ub = *(const uint2*)(S_yb + off);
        float2 a01 = __bfloat1622float2(*(__nv_bfloat162*)&ua.x);
        float2 a23 = __bfloat1622float2(*(__nv_bfloat162*)&ua.y);
        float2 b01 = __bfloat1622float2(*(__nv_bfloat162*)&ub.x);
        float2 b23 = __bfloat1622float2(*(__nv_bfloat162*)&ub.y);
        stage4(As + m*128, (m&1)<<4, c,
               a01.x+b01.x, a01.y+b01.y, a23.x+b23.x, a23.y+b23.y);
    }
    __syncthreads();

    float acc[2][3][4] = {};
    gemm_ldgB<8,128>(As, 128, WoP, wm, wn, gid, tq, acc);

    #pragma unroll
    for (int mt = 0; mt < 2; mt++) {
        int r = wm*32 + mt*16 + gid;
        #pragma unroll
        for (int nt = 0; nt < 3; nt++) {
            int c = wn*24 + nt*8 + tq*2;
            x1s[r*100 + c]     = acc[mt][nt][0];
            x1s[r*100 + c + 1] = acc[mt][nt][1];
            x1s[(r+8)*100 + c]     = acc[mt][nt][2];
            x1s[(r+8)*100 + c + 1] = acc[mt][nt][3];
        }
    }
    __syncthreads();

    for (int r = warp; r < 64; r += 8) {
        int gm = m_base + r;
        size_t base = (size_t)Goff[gm];
        size_t xb = base*96;
        float v0 = x1s[r*100 + lane*3 + 0] + x[xb + lane*3 + 0];
        float v1 = x1s[r*100 + lane*3 + 1] + x[xb + lane*3 + 1];
        float v2 = x1s[r*100 + lane*3 + 2] + x[xb + lane*3 + 2];
        x1s[r*100 + lane*3 + 0] = v0;
        x1s[r*100 + lane*3 + 1] = v1;
        x1s[r*100 + lane*3 + 2] = v2;
        float s1 = v0+v1+v2, s2 = v0*v0+v1*v1+v2*v2;
        #pragma unroll
        for (int o = 16; o > 0; o >>= 1) {
            s1 += __shfl_xor_sync(0xffffffffu, s1, o);
            s2 += __shfl_xor_sync(0xffffffffu, s2, o);
        }
        float mu  = s1 * (1.0f/96.0f);
        float var = s2 * (1.0f/96.0f) - mu*mu;
        float rs  = rsqrtf(var + 1e-5f);
        size_t sbase = base*8;
        float xs[8];
        #pragma unroll
        for (int k = 0; k < 8; k++) xs[k] = xstat[sbase + k];
        int swr = (r & 1) << 4;
        #pragma unroll
        for (int i2 = 0; i2 < 3; i2++) {
            int jj = lane*3 + i2;
            float a = loan2_b[jj];
            #pragma unroll
            for (int k = 0; k < 8; k++) a = fmaf(xs[k], loan2_w[k*96 + jj], a);
            float vv = (i2 == 0) ? v0 : ((i2 == 1) ? v1 : v2);
            tts[r*96 + (kperm16(jj) ^ swr)] = f2tf32((vv - mu)*rs + ftanh(a));
        }
    }
    __syncthreads();

    float acc1[2][3][4] = {};
    gemm_ldgB<6,96>(tts, 96, W1P, wm, wn, gid, tq, acc1);
    __syncthreads();

    #pragma unroll
    for (int mt = 0; mt < 2; mt++) {
        int r = wm*32 + mt*16 + gid;
        int swr = (r & 1) << 4;
        #pragma unroll
        for (int nt = 0; nt < 3; nt++) {
            int c = wn*24 + nt*8 + tq*2;
            float bb0 = b1[c], bb1 = b1[c+1];
            hs[r*96 + (kperm16(c)   ^ swr)] = f2tf32(geluf(acc1[mt][nt][0] + bb0));
            hs[r*96 + (kperm16(c+1) ^ swr)] = f2tf32(geluf(acc1[mt][nt][1] + bb1));
            hs[(r+8)*96 + (kperm16(c)   ^ swr)] = f2tf32(geluf(acc1[mt][nt][2] + bb0));
            hs[(r+8)*96 + (kperm16(c+1) ^ swr)] = f2tf32(geluf(acc1[mt][nt][3] + bb1));
        }
    }
    __syncthreads();

    float acc2[2][3][4] = {};
    gemm_ldgB<6,96>(hs, 96, W2P, wm, wn, gid, tq, acc2);

    #pragma unroll
    for (int mt = 0; mt < 2; mt++) {
        int r = wm*32 + mt*16 + gid;
        int gm0 = m_base + r, gm8 = gm0 + 8;
        #pragma unroll
        for (int nt = 0; nt < 3; nt++) {
            int c = wn*24 + nt*8 + tq*2;
            float bb0 = b2[c], bb1 = b2[c+1];
            *(float2*)(out + (size_t)gm0*96 + c) = make_float2(
                acc2[mt][nt][0] + bb0 + x1s[r*100 + c],
                acc2[mt][nt][1] + bb1 + x1s[r*100 + c + 1]);
            *(float2*)(out + (size_t)gm8*96 + c) = make_float2(
                acc2[mt][nt][2] + bb0 + x1s[(r+8)*100 + c],
                acc2[mt][nt][3] + bb1 + x1s[(r+8)*100 + c + 1]);
        }
    }
}

// ================= launcher =================
extern "C" void kernel_launch(void* const* d_in, const int* in_sizes, int n_in,
                              void* d_out, int out_size)
{
    const float* x       = (const float*)d_in[0];
    const float* xstat   = (const float*)d_in[1];
    const float* xhres   = (const float*)d_in[2];
    const int*   curves  = (const int*)  d_in[3];
    const float* embed_w = (const float*)d_in[4];
    const float* embed_b = (const float*)d_in[5];
    const float* loan1_w = (const float*)d_in[6];
    const float* loan1_b = (const float*)d_in[7];
    const float* loan2_w = (const float*)d_in[8];
    const float* loan2_b = (const float*)d_in[9];
    const float* in_proj = (const float*)d_in[10];
    const float* cw_f  = (const float*)d_in[11];
    const float* cb_f  = (const float*)d_in[12];
    const float* dtb_f = (const float*)d_in[13];
    const float* al_f  = (const float*)d_in[14];
    const float* Dp_f  = (const float*)d_in[15];
    const float* nw_f  = (const float*)d_in[16];
    const float* cw_b  = (const float*)d_in[17];
    const float* cb_b  = (const float*)d_in[18];
    const float* dtb_b = (const float*)d_in[19];
    const float* al_b  = (const float*)d_in[20];
    const float* Dp_b  = (const float*)d_in[21];
    const float* nw_b  = (const float*)d_in[22];
    const float* Wo    = (const float*)d_in[23];
    const float* W1    = (const float*)d_in[24];
    const float* b1    = (const float*)d_in[25];
    const float* W2    = (const float*)d_in[26];
    const float* b2    = (const float*)d_in[27];
    float* out = (float*)d_out;

    const int smem012 = (64*268 + 64*128 + 960) * 4;   // 105216
    const int smem34  = (64*128 + 64*100) * 4;         // 58368

    cudaFuncSetAttribute(k012_fused, cudaFuncAttributeMaxDynamicSharedMemorySize, smem012);
    cudaFuncSetAttribute(k34_fused,  cudaFuncAttributeMaxDynamicSharedMemorySize, smem34);

    kprep<<<NTOK/256, 256>>>(in_proj, Wo, W1, W2, curves);
    khr<<<NTOK*8/256, 256>>>(xhres, embed_w, embed_b);

    k012_fused<<<4096, 256, smem012>>>(x, xstat, loan1_w, loan1_b,
                                       cw_f, cb_f, dtb_f, al_f, Dp_f, nw_f,
                                       cw_b, cb_b, dtb_b, al_b, Dp_b, nw_b);

    k34_fused<<<NTOK/64, 256, smem34>>>(x, xstat, loan2_w, loan2_b, b1, b2, out);
}